// round 1
// baseline (speedup 1.0000x reference)
#include <cuda_runtime.h>

#define NQ   12
#define DIM  4096
#define NT   512

struct CM { float2 m[4]; };  // row-major complex 2x2: m[i*2+j]

__device__ __forceinline__ float2 cmul(float2 a, float2 b) {
    return make_float2(a.x*b.x - a.y*b.y, a.x*b.y + a.y*b.x);
}
__device__ __forceinline__ float2 cadd(float2 a, float2 b) {
    return make_float2(a.x + b.x, a.y + b.y);
}
__device__ __forceinline__ CM mm(const CM& A, const CM& B) {
    CM C;
#pragma unroll
    for (int i = 0; i < 2; i++)
#pragma unroll
        for (int j = 0; j < 2; j++)
            C.m[i*2+j] = cadd(cmul(A.m[i*2+0], B.m[0*2+j]),
                              cmul(A.m[i*2+1], B.m[1*2+j]));
    return C;
}
__device__ __forceinline__ CM RX(float t) {
    float s, c; sincosf(0.5f*t, &s, &c);
    CM M;
    M.m[0] = make_float2(c, 0.f);  M.m[1] = make_float2(0.f, -s);
    M.m[2] = make_float2(0.f, -s); M.m[3] = make_float2(c, 0.f);
    return M;
}
__device__ __forceinline__ CM RY(float t) {
    float s, c; sincosf(0.5f*t, &s, &c);
    CM M;
    M.m[0] = make_float2(c, 0.f);  M.m[1] = make_float2(-s, 0.f);
    M.m[2] = make_float2(s, 0.f);  M.m[3] = make_float2(c, 0.f);
    return M;
}
__device__ __forceinline__ CM RZ(float t) {
    float s, c; sincosf(0.5f*t, &s, &c);
    CM M;
    M.m[0] = make_float2(c, -s);   M.m[1] = make_float2(0.f, 0.f);
    M.m[2] = make_float2(0.f, 0.f); M.m[3] = make_float2(c, s);
    return M;
}

__global__ void __launch_bounds__(NT)
qsim_kernel(const float* __restrict__ data,
            const float* __restrict__ es,      // encoding_scale [12,3]
            const float* __restrict__ eb,      // encoding_bias  [12,3]
            const float* __restrict__ eta,     // [1,3]
            const float* __restrict__ ew_zz,   // [1,12]
            const float* __restrict__ ew_xx,
            const float* __restrict__ ew_yy,
            const float* __restrict__ nb_z,    // [1,12]
            const float* __restrict__ nb_x,
            const float* __restrict__ nb_y,
            const float* __restrict__ rots,    // [1,3,12,3]
            float* __restrict__ out)           // [64,12]
{
    __shared__ float sRe[DIM];
    __shared__ float sIm[DIM];
    __shared__ float2 gEnc[NQ][4];
    __shared__ float2 gFus[NQ][4];
    __shared__ float isC[NQ], isS[NQ];
    __shared__ float sums[NQ];

    const int b = blockIdx.x;
    const int t = threadIdx.x;

    // init |0...0>
#pragma unroll
    for (int j = 0; j < DIM / NT; j++) {
        int i = t + j * NT;
        sRe[i] = (i == 0) ? 1.0f : 0.0f;
        sIm[i] = 0.0f;
    }
    if (t < NQ) sums[t] = 0.0f;

    for (int blk = 0; blk < 3; blk++) {
        // ---- per-block gate table computation (threads 0..11) ----
        if (t < NQ) {
            const int q = t;
            float d  = data[b*NQ + q];
            float ax = es[q*3+0]*d + eb[q*3+0];
            float ay = es[q*3+1]*d + eb[q*3+1];
            float az = es[q*3+2]*d + eb[q*3+2];
            CM M;
            if (blk == 0)      M = mm(RZ(az), mm(RY(ay), RX(ax)));  // 'full'
            else if (blk == 1) M = mm(RY(ay), RX(ax));              // 'xy'
            else               M = mm(RZ(az), RY(ay));              // 'yz'
#pragma unroll
            for (int k = 0; k < 4; k++) gEnc[q][k] = M.m[k];

            float bias = (blk == 0) ? nb_z[q] : (blk == 1) ? nb_x[q] : nb_y[q];
            CM Mb = (blk == 0) ? RZ(bias) : (blk == 1) ? RX(bias) : RY(bias);
            const float* rr = rots + blk*(NQ*3) + q*3;
            CM M2 = mm(RZ(rr[2]), mm(RY(rr[1]), mm(RX(rr[0]), Mb)));
#pragma unroll
            for (int k = 0; k < 4; k++) gFus[q][k] = M2.m[k];

            // ising params (edge e = q)
            float ew = (blk == 0) ? ew_zz[q] : (blk == 1) ? ew_xx[q] : ew_yy[q];
            float th = eta[blk] * ew;
            float s, c; sincosf(0.5f*th, &s, &c);
            isC[q] = c; isS[q] = s;
        }
        __syncthreads();

        // ---- data-encoding fused 1q gates (apply_1q: qubit q at bit q) ----
        for (int q = 0; q < NQ; q++) {
            const float2 g00 = gEnc[q][0], g01 = gEnc[q][1];
            const float2 g10 = gEnc[q][2], g11 = gEnc[q][3];
            const int bit = 1 << q;
#pragma unroll
            for (int j = 0; j < (DIM/2)/NT; j++) {
                int p  = t + j * NT;
                int i0 = ((p & ~(bit-1)) << 1) | (p & (bit-1));
                int i1 = i0 | bit;
                float2 a0 = make_float2(sRe[i0], sIm[i0]);
                float2 a1 = make_float2(sRe[i1], sIm[i1]);
                float2 n0 = cadd(cmul(g00, a0), cmul(g01, a1));
                float2 n1 = cadd(cmul(g10, a0), cmul(g11, a1));
                sRe[i0] = n0.x; sIm[i0] = n0.y;
                sRe[i1] = n1.x; sIm[i1] = n1.y;
            }
            __syncthreads();
        }

        // ---- Ising 2q gates (apply_2q: qubit q at bit 11-q) ----
        for (int e = 0; e < NQ; e++) {
            const int q1 = (e < 11) ? e     : 0;
            const int q2 = (e < 11) ? e + 1 : 11;
            const int b1 = 11 - q1;   // high bit (gate index A)
            const int b2 = 11 - q2;   // low bit  (gate index B)
            const float c = isC[e], s = isS[e];
            if (blk == 0) {
                // ZZ: diagonal phase, di = {-s, s, s, -s} over x = 2A+B
#pragma unroll
                for (int j = 0; j < DIM/NT; j++) {
                    int k = t + j * NT;
                    int A = (k >> b1) & 1, B = (k >> b2) & 1;
                    float di = (A == B) ? -s : s;
                    float re = sRe[k], im = sIm[k];
                    sRe[k] = re*c - im*di;
                    sIm[k] = re*di + im*c;
                }
            } else {
                // XX: new = c*a  - i*s*partner        (partner = flip both bits)
                // YY: new = c*a +/- i*s*partner  (+ for pair {0,3}, - for {1,2})
                const int bm1 = 1 << b1;
                const int mask = bm1 | (1 << b2);
#pragma unroll
                for (int j = 0; j < (DIM/2)/NT; j++) {
                    int p  = t + j * NT;
                    int k0 = ((p & ~(bm1-1)) << 1) | (p & (bm1-1));  // bit b1 = 0
                    int k1 = k0 ^ mask;
                    float r0 = sRe[k0], i0 = sIm[k0];
                    float r1 = sRe[k1], i1 = sIm[k1];
                    float ss = (blk == 1) ? -s
                                          : (((k0 >> b2) & 1) ? -s : s);
                    sRe[k0] = c*r0 - ss*i1;
                    sIm[k0] = c*i0 + ss*r1;
                    sRe[k1] = c*r1 - ss*i0;
                    sIm[k1] = c*i1 + ss*r0;
                }
            }
            __syncthreads();
        }

        // ---- fused bias + trainable-rot 1q gates (bit q) ----
        for (int q = 0; q < NQ; q++) {
            const float2 g00 = gFus[q][0], g01 = gFus[q][1];
            const float2 g10 = gFus[q][2], g11 = gFus[q][3];
            const int bit = 1 << q;
#pragma unroll
            for (int j = 0; j < (DIM/2)/NT; j++) {
                int p  = t + j * NT;
                int i0 = ((p & ~(bit-1)) << 1) | (p & (bit-1));
                int i1 = i0 | bit;
                float2 a0 = make_float2(sRe[i0], sIm[i0]);
                float2 a1 = make_float2(sRe[i1], sIm[i1]);
                float2 n0 = cadd(cmul(g00, a0), cmul(g01, a1));
                float2 n1 = cadd(cmul(g10, a0), cmul(g11, a1));
                sRe[i0] = n0.x; sIm[i0] = n0.y;
                sRe[i1] = n1.x; sIm[i1] = n1.y;
            }
            __syncthreads();
        }

        // ---- CNOT ring (apply_2q sorted: control = bit 11-min, target = bit 11-max) ----
        for (int q = 0; q < NQ; q++) {
            const int qq = (q + 1) % NQ;
            const int q1 = (q < qq) ? q  : qq;
            const int q2 = (q < qq) ? qq : q;
            const int bc  = 11 - q1;   // control bit (high)
            const int btg = 11 - q2;   // target bit  (low)
            const int lo = btg, hi = bc;
            const int cb = 1 << bc, tb = 1 << btg;
#pragma unroll
            for (int j = 0; j < (DIM/4)/NT; j++) {
                int p    = t + j * NT;
                int low  = p & ((1 << lo) - 1);
                int mid  = (p >> lo) & ((1 << (hi - 1 - lo)) - 1);
                int high = p >> (hi - 1);
                int k  = (high << (hi + 1)) | (mid << (lo + 1)) | low | cb; // control=1, target=0
                int kp = k | tb;                                           // control=1, target=1
                float r = sRe[k]; sRe[k] = sRe[kp]; sRe[kp] = r;
                float i = sIm[k]; sIm[k] = sIm[kp]; sIm[kp] = i;
            }
            __syncthreads();
        }
    }

    // ---- measurement: out[b,i] = sum_k |amp_k|^2 * (1 - 2*bit(11-i, k)) ----
    float acc[NQ];
#pragma unroll
    for (int i = 0; i < NQ; i++) acc[i] = 0.0f;
#pragma unroll
    for (int j = 0; j < DIM/NT; j++) {
        int k = t + j * NT;
        float p = sRe[k]*sRe[k] + sIm[k]*sIm[k];
#pragma unroll
        for (int i = 0; i < NQ; i++)
            acc[i] += ((k >> (11 - i)) & 1) ? -p : p;
    }
#pragma unroll
    for (int off = 16; off > 0; off >>= 1)
#pragma unroll
        for (int i = 0; i < NQ; i++)
            acc[i] += __shfl_down_sync(0xffffffffu, acc[i], off);
    if ((t & 31) == 0) {
#pragma unroll
        for (int i = 0; i < NQ; i++)
            atomicAdd(&sums[i], acc[i]);
    }
    __syncthreads();
    if (t < NQ) out[b*NQ + t] = sums[t];
}

extern "C" void kernel_launch(void* const* d_in, const int* in_sizes, int n_in,
                              void* d_out, int out_size) {
    const float* data   = (const float*)d_in[0];
    const float* es     = (const float*)d_in[1];
    const float* eb     = (const float*)d_in[2];
    const float* eta    = (const float*)d_in[3];
    const float* ew_zz  = (const float*)d_in[4];
    const float* ew_xx  = (const float*)d_in[5];
    const float* ew_yy  = (const float*)d_in[6];
    const float* nb_z   = (const float*)d_in[7];
    const float* nb_x   = (const float*)d_in[8];
    const float* nb_y   = (const float*)d_in[9];
    const float* rots   = (const float*)d_in[10];
    float* out = (float*)d_out;

    int B = in_sizes[0] / NQ;   // 64
    qsim_kernel<<<B, NT>>>(data, es, eb, eta, ew_zz, ew_xx, ew_yy,
                           nb_z, nb_x, nb_y, rots, out);
}

// round 2
// speedup vs baseline: 1.4304x; 1.4304x over previous
#include <cuda_runtime.h>

#define NQ   12
#define DIM  4096
#define NT   1024

struct Masks {
    unsigned short m1[3][NQ];   // stored-coord pair mask for logical 1q gate on qubit q, block b
    unsigned short R1[3][NQ];   // row mask: parity(k & R1) = logical bit q of F^b(k)
    unsigned short mE[3][NQ];   // stored-coord pair mask for Ising edge e
    unsigned short XE[3][NQ];   // row mask for edge sign: parity = (bitA ^ bitB) of F^b(k)
    unsigned short RM[NQ];      // measurement rows of F^3
};

struct CM { float2 m[4]; };

__device__ __forceinline__ float2 cxmul(float2 a, float2 b) {
    return make_float2(a.x*b.x - a.y*b.y, a.x*b.y + a.y*b.x);
}
__device__ __forceinline__ float2 cxadd(float2 a, float2 b) {
    return make_float2(a.x + b.x, a.y + b.y);
}
__device__ __forceinline__ CM mm(const CM& A, const CM& B) {
    CM C;
#pragma unroll
    for (int i = 0; i < 2; i++)
#pragma unroll
        for (int j = 0; j < 2; j++)
            C.m[i*2+j] = cxadd(cxmul(A.m[i*2+0], B.m[0*2+j]),
                               cxmul(A.m[i*2+1], B.m[1*2+j]));
    return C;
}
__device__ __forceinline__ CM RX(float t) {
    float s, c; sincosf(0.5f*t, &s, &c);
    CM M;
    M.m[0] = make_float2(c, 0.f);  M.m[1] = make_float2(0.f, -s);
    M.m[2] = make_float2(0.f, -s); M.m[3] = make_float2(c, 0.f);
    return M;
}
__device__ __forceinline__ CM RY(float t) {
    float s, c; sincosf(0.5f*t, &s, &c);
    CM M;
    M.m[0] = make_float2(c, 0.f);  M.m[1] = make_float2(-s, 0.f);
    M.m[2] = make_float2(s, 0.f);  M.m[3] = make_float2(c, 0.f);
    return M;
}
__device__ __forceinline__ CM RZ(float t) {
    float s, c; sincosf(0.5f*t, &s, &c);
    CM M;
    M.m[0] = make_float2(c, -s);    M.m[1] = make_float2(0.f, 0.f);
    M.m[2] = make_float2(0.f, 0.f); M.m[3] = make_float2(c, s);
    return M;
}

// canonical complex 2x2 apply on (a0 = logical-0, a1 = logical-1)
__device__ __forceinline__ void apply2(const float2 g[4], float2 &a0, float2 &a1) {
    float2 n0, n1;
    n0.x = g[0].x*a0.x - g[0].y*a0.y + g[1].x*a1.x - g[1].y*a1.y;
    n0.y = g[0].x*a0.y + g[0].y*a0.x + g[1].x*a1.y + g[1].y*a1.x;
    n1.x = g[2].x*a0.x - g[2].y*a0.y + g[3].x*a1.x - g[3].y*a1.y;
    n1.y = g[2].x*a0.y + g[2].y*a0.x + g[3].x*a1.y + g[3].y*a1.x;
    a0 = n0; a1 = n1;
}

// XX/YY pairwise mix: a' = c*a - i*ss*b (and symmetric), matching reference algebra
__device__ __forceinline__ void applyMix(float c, float ss, float2 &a, float2 &b) {
    float2 na, nb;
    na.x = c*a.x - ss*b.y;  na.y = c*a.y + ss*b.x;
    nb.x = c*b.x - ss*a.y;  nb.y = c*b.y + ss*a.x;
    a = na; b = nb;
}

// insert zero bits at positions lo < hi (final coordinates)
__device__ __forceinline__ unsigned insert2(unsigned i, int lo, int hi) {
    unsigned p = ((i >> lo) << (lo + 1)) | (i & ((1u << lo) - 1u));
    p = ((p >> hi) << (hi + 1)) | (p & ((1u << hi) - 1u));
    return p;
}

__global__ void __launch_bounds__(NT)
qsim_kernel(const float* __restrict__ data,
            const float* __restrict__ es,
            const float* __restrict__ eb,
            const float* __restrict__ eta,
            const float* __restrict__ ew_zz,
            const float* __restrict__ ew_xx,
            const float* __restrict__ ew_yy,
            const float* __restrict__ nb_z,
            const float* __restrict__ nb_x,
            const float* __restrict__ nb_y,
            const float* __restrict__ rots,
            Masks MK,
            float* __restrict__ out)
{
    __shared__ float2 amp[DIM];
    __shared__ float2 gT1[NQ][4];   // encoding gates
    __shared__ float2 gT2[NQ][4];   // bias+rots fused gates
    __shared__ float  sC[NQ], sS[NQ], sH[NQ];
    __shared__ float  red[32][NQ];

    const int b = blockIdx.x;
    const int t = threadIdx.x;

#pragma unroll
    for (int j = 0; j < DIM / NT; j++) {
        int i = t + j * NT;
        amp[i] = make_float2((i == 0) ? 1.0f : 0.0f, 0.0f);
    }

    for (int blk = 0; blk < 3; blk++) {
        // ---- per-block gate tables (threads 0..11) ----
        if (t < NQ) {
            const int q = t;
            float d  = data[b*NQ + q];
            float ax = es[q*3+0]*d + eb[q*3+0];
            float ay = es[q*3+1]*d + eb[q*3+1];
            float az = es[q*3+2]*d + eb[q*3+2];
            CM M;
            if (blk == 0)      M = mm(RZ(az), mm(RY(ay), RX(ax)));
            else if (blk == 1) M = mm(RY(ay), RX(ax));
            else               M = mm(RZ(az), RY(ay));
#pragma unroll
            for (int k = 0; k < 4; k++) gT1[q][k] = M.m[k];

            float bias = (blk == 0) ? nb_z[q] : (blk == 1) ? nb_x[q] : nb_y[q];
            CM Mb = (blk == 0) ? RZ(bias) : (blk == 1) ? RX(bias) : RY(bias);
            const float* rr = rots + blk*(NQ*3) + q*3;
            CM M2 = mm(RZ(rr[2]), mm(RY(rr[1]), mm(RX(rr[0]), Mb)));
#pragma unroll
            for (int k = 0; k < 4; k++) gT2[q][k] = M2.m[k];

            float ew = (blk == 0) ? ew_zz[q] : (blk == 1) ? ew_xx[q] : ew_yy[q];
            float h = 0.5f * eta[blk] * ew;
            float s, c; sincosf(h, &s, &c);
            sC[q] = c; sS[q] = s; sH[q] = h;
        }
        __syncthreads();

        // ---- encoding: 6 quad sweeps (qubits 2g, 2g+1) ----
        for (int g = 0; g < 6; g++) {
            const int qA = 2*g, qB = 2*g + 1;
            const unsigned mA = MK.m1[blk][qA], RA = MK.R1[blk][qA];
            const unsigned mB = MK.m1[blk][qB], RB = MK.R1[blk][qB];
            const int hA = 31 - __clz((int)mA), hB = 31 - __clz((int)mB);
            const int lo = hA < hB ? hA : hB, hi = hA < hB ? hB : hA;
            float2 gA[4], gB[4];
#pragma unroll
            for (int k = 0; k < 4; k++) { gA[k] = gT1[qA][k]; gB[k] = gT1[qB][k]; }
            unsigned p = insert2((unsigned)t, lo, hi);
            unsigned base = p;
            if (__popc(p & RA) & 1) base ^= mA;
            if (__popc(p & RB) & 1) base ^= mB;
            const unsigned i10 = base ^ mA, i01 = base ^ mB, i11 = base ^ mA ^ mB;
            float2 a00 = amp[base], a10 = amp[i10], a01 = amp[i01], a11 = amp[i11];
            apply2(gA, a00, a10); apply2(gA, a01, a11);
            apply2(gB, a00, a01); apply2(gB, a10, a11);
            amp[base] = a00; amp[i10] = a10; amp[i01] = a01; amp[i11] = a11;
            __syncthreads();
        }

        // ---- Ising ----
        if (blk == 0) {
            // ZZ: one fused diagonal sweep
            float h[NQ];
#pragma unroll
            for (int e = 0; e < NQ; e++) h[e] = sH[e];
            unsigned short XE0[NQ];
#pragma unroll
            for (int e = 0; e < NQ; e++) XE0[e] = MK.XE[0][e];
#pragma unroll
            for (int j = 0; j < DIM / NT; j++) {
                int k = t + j * NT;
                float phi = 0.0f;
#pragma unroll
                for (int e = 0; e < NQ; e++)
                    phi += (__popc((unsigned)k & XE0[e]) & 1) ? h[e] : -h[e];
                float sp, cp;
                __sincosf(phi, &sp, &cp);
                float2 a = amp[k];
                amp[k] = make_float2(a.x*cp - a.y*sp, a.x*sp + a.y*cp);
            }
            __syncthreads();
        } else {
            // XX (blk1) / YY (blk2): 6 quad sweeps, edges (2g, 2g+1)
            for (int g = 0; g < 6; g++) {
                const int e1 = 2*g, e2 = 2*g + 1;
                const unsigned m1 = MK.mE[blk][e1], m2 = MK.mE[blk][e2];
                const float c1 = sC[e1], s1 = sS[e1];
                const float c2 = sC[e2], s2 = sS[e2];
                const int h1 = 31 - __clz((int)m1), h2 = 31 - __clz((int)m2);
                const int lo = h1 < h2 ? h1 : h2, hi = h1 < h2 ? h2 : h1;
                unsigned p = insert2((unsigned)t, lo, hi);
                const unsigned iA = p ^ m1, iB = p ^ m2, iC = p ^ m1 ^ m2;
                float2 r0 = amp[p], r1 = amp[iA], r2 = amp[iB], r3 = amp[iC];
                if (blk == 1) {
                    applyMix(c1, -s1, r0, r1); applyMix(c1, -s1, r2, r3);
                    applyMix(c2, -s2, r0, r2); applyMix(c2, -s2, r1, r3);
                } else {
                    const unsigned X1 = MK.XE[2][e1], X2 = MK.XE[2][e2];
                    const unsigned adj1 = __popc(m2 & X1) & 1;
                    const unsigned adj2 = __popc(m1 & X2) & 1;
                    unsigned t1 = __popc(p & X1) & 1;
                    applyMix(c1, t1 ? -s1 : s1, r0, r1);
                    applyMix(c1, (t1 ^ adj1) ? -s1 : s1, r2, r3);
                    unsigned t2 = __popc(p & X2) & 1;
                    applyMix(c2, t2 ? -s2 : s2, r0, r2);
                    applyMix(c2, (t2 ^ adj2) ? -s2 : s2, r1, r3);
                }
                amp[p] = r0; amp[iA] = r1; amp[iB] = r2; amp[iC] = r3;
                __syncthreads();
            }
        }

        // ---- bias + trainable rots: 6 quad sweeps ----
        for (int g = 0; g < 6; g++) {
            const int qA = 2*g, qB = 2*g + 1;
            const unsigned mA = MK.m1[blk][qA], RA = MK.R1[blk][qA];
            const unsigned mB = MK.m1[blk][qB], RB = MK.R1[blk][qB];
            const int hA = 31 - __clz((int)mA), hB = 31 - __clz((int)mB);
            const int lo = hA < hB ? hA : hB, hi = hA < hB ? hB : hA;
            float2 gA[4], gB[4];
#pragma unroll
            for (int k = 0; k < 4; k++) { gA[k] = gT2[qA][k]; gB[k] = gT2[qB][k]; }
            unsigned p = insert2((unsigned)t, lo, hi);
            unsigned base = p;
            if (__popc(p & RA) & 1) base ^= mA;
            if (__popc(p & RB) & 1) base ^= mB;
            const unsigned i10 = base ^ mA, i01 = base ^ mB, i11 = base ^ mA ^ mB;
            float2 a00 = amp[base], a10 = amp[i10], a01 = amp[i01], a11 = amp[i11];
            apply2(gA, a00, a10); apply2(gA, a01, a11);
            apply2(gB, a00, a01); apply2(gB, a10, a11);
            amp[base] = a00; amp[i10] = a10; amp[i01] = a01; amp[i11] = a11;
            __syncthreads();
        }
        // CNOT ring: folded into mask transforms of the next block (zero sweeps)
    }

    // ---- measurement: logical index = F^3(stored index); sign = parity(k & RM[i]) ----
    float acc[NQ];
#pragma unroll
    for (int i = 0; i < NQ; i++) acc[i] = 0.0f;
#pragma unroll
    for (int j = 0; j < DIM / NT; j++) {
        int k = t + j * NT;
        float2 a = amp[k];
        float pr = a.x*a.x + a.y*a.y;
#pragma unroll
        for (int i = 0; i < NQ; i++)
            acc[i] += (__popc((unsigned)k & MK.RM[i]) & 1) ? -pr : pr;
    }
#pragma unroll
    for (int off = 16; off > 0; off >>= 1)
#pragma unroll
        for (int i = 0; i < NQ; i++)
            acc[i] += __shfl_down_sync(0xffffffffu, acc[i], off);
    const int wid = t >> 5;
    if ((t & 31) == 0) {
#pragma unroll
        for (int i = 0; i < NQ; i++) red[wid][i] = acc[i];
    }
    __syncthreads();
    if (t < NQ) {
        float s = 0.0f;
#pragma unroll
        for (int w = 0; w < NT/32; w++) s += red[w][t];
        out[b*NQ + t] = s;
    }
}

// ---- host: GF(2) linear algebra of the CNOT ring ----
// Ring forward map on indices: F(k); gather/mask-transform map: G = F^{-1}.
static inline unsigned Gm(unsigned j) {
    unsigned r = (j ^ (j >> 1)) & 0xFFFu;
    r ^= (j >> 11) & 1u;
    return r;
}
static inline unsigned Fm(unsigned k) {
    unsigned p = k;
    p ^= p >> 1; p ^= p >> 2; p ^= p >> 4; p ^= p >> 8;
    p &= 0xFFFu;
    return (p & 0xFFEu) | ((p ^ (k >> 11)) & 1u);
}

extern "C" void kernel_launch(void* const* d_in, const int* in_sizes, int n_in,
                              void* d_out, int out_size) {
    const float* data   = (const float*)d_in[0];
    const float* es     = (const float*)d_in[1];
    const float* eb     = (const float*)d_in[2];
    const float* eta    = (const float*)d_in[3];
    const float* ew_zz  = (const float*)d_in[4];
    const float* ew_xx  = (const float*)d_in[5];
    const float* ew_yy  = (const float*)d_in[6];
    const float* nb_z   = (const float*)d_in[7];
    const float* nb_x   = (const float*)d_in[8];
    const float* nb_y   = (const float*)d_in[9];
    const float* rots   = (const float*)d_in[10];
    float* out = (float*)d_out;

    Masks MK;
    unsigned rows[4][12];
    for (int p = 0; p < 4; p++) {
        unsigned col[12];
        for (int j = 0; j < 12; j++) {
            unsigned v = 1u << j;
            for (int it = 0; it < p; it++) v = Fm(v);
            col[j] = v;
        }
        for (int q = 0; q < 12; q++) {
            unsigned r = 0;
            for (int j = 0; j < 12; j++) r |= ((col[j] >> q) & 1u) << j;
            rows[p][q] = r;
        }
    }
    for (int blk = 0; blk < 3; blk++) {
        for (int q = 0; q < 12; q++) {
            unsigned m = 1u << q;
            for (int it = 0; it < blk; it++) m = Gm(m);
            MK.m1[blk][q] = (unsigned short)m;
            MK.R1[blk][q] = (unsigned short)rows[blk][q];
        }
        for (int e = 0; e < 12; e++) {
            unsigned a  = (e < 11) ? (unsigned)(11 - e) : 11u;
            unsigned b2 = (e < 11) ? (unsigned)(10 - e) : 0u;
            unsigned M = (1u << a) | (1u << b2);
            unsigned m = M;
            for (int it = 0; it < blk; it++) m = Gm(m);
            MK.mE[blk][e] = (unsigned short)m;
            MK.XE[blk][e] = (unsigned short)(rows[blk][a] ^ rows[blk][b2]);
        }
    }
    for (int i = 0; i < 12; i++) MK.RM[i] = (unsigned short)rows[3][11 - i];

    int B = in_sizes[0] / NQ;
    qsim_kernel<<<B, NT>>>(data, es, eb, eta, ew_zz, ew_xx, ew_yy,
                           nb_z, nb_x, nb_y, rots, MK, out);
}

// round 3
// speedup vs baseline: 1.5324x; 1.0713x over previous
#include <cuda_runtime.h>
#include <cooperative_groups.h>
namespace cg = cooperative_groups;

#define NQ    12
#define HDIM  2048      // per-CTA half state
#define NT    512

struct Plan {
    unsigned short m1[3][NQ], R1[3][NQ];   // 1q pair masks / sign rows (12-bit)
    unsigned short mE[3][NQ], XE[3][NQ];   // edge pair masks / sign rows
    unsigned short RM[NQ];                 // measurement rows
    unsigned char  ord1[3][NQ];            // locals first, then crosses
    unsigned char  ordE[3][NQ];
    int n1loc[3], nEloc[3];
};

struct CM { float2 m[4]; };

__device__ __forceinline__ float2 cxmul(float2 a, float2 b) {
    return make_float2(a.x*b.x - a.y*b.y, a.x*b.y + a.y*b.x);
}
__device__ __forceinline__ float2 cxadd(float2 a, float2 b) {
    return make_float2(a.x + b.x, a.y + b.y);
}
__device__ __forceinline__ CM mm(const CM& A, const CM& B) {
    CM C;
#pragma unroll
    for (int i = 0; i < 2; i++)
#pragma unroll
        for (int j = 0; j < 2; j++)
            C.m[i*2+j] = cxadd(cxmul(A.m[i*2+0], B.m[0*2+j]),
                               cxmul(A.m[i*2+1], B.m[1*2+j]));
    return C;
}
__device__ __forceinline__ CM RX(float t) {
    float s, c; sincosf(0.5f*t, &s, &c);
    CM M;
    M.m[0] = make_float2(c,0.f);  M.m[1] = make_float2(0.f,-s);
    M.m[2] = make_float2(0.f,-s); M.m[3] = make_float2(c,0.f);
    return M;
}
__device__ __forceinline__ CM RY(float t) {
    float s, c; sincosf(0.5f*t, &s, &c);
    CM M;
    M.m[0] = make_float2(c,0.f); M.m[1] = make_float2(-s,0.f);
    M.m[2] = make_float2(s,0.f); M.m[3] = make_float2(c,0.f);
    return M;
}
__device__ __forceinline__ CM RZ(float t) {
    float s, c; sincosf(0.5f*t, &s, &c);
    CM M;
    M.m[0] = make_float2(c,-s);    M.m[1] = make_float2(0.f,0.f);
    M.m[2] = make_float2(0.f,0.f); M.m[3] = make_float2(c,s);
    return M;
}

__device__ __forceinline__ void apply2(const float2 g[4], float2 &a0, float2 &a1) {
    float2 n0, n1;
    n0.x = g[0].x*a0.x - g[0].y*a0.y + g[1].x*a1.x - g[1].y*a1.y;
    n0.y = g[0].x*a0.y + g[0].y*a0.x + g[1].x*a1.y + g[1].y*a1.x;
    n1.x = g[2].x*a0.x - g[2].y*a0.y + g[3].x*a1.x - g[3].y*a1.y;
    n1.y = g[2].x*a0.y + g[2].y*a0.x + g[3].x*a1.y + g[3].y*a1.x;
    a0 = n0; a1 = n1;
}
__device__ __forceinline__ void applyMix(float c, float ss, float2 &a, float2 &b) {
    float2 na, nb;
    na.x = c*a.x - ss*b.y;  na.y = c*a.y + ss*b.x;
    nb.x = c*b.x - ss*a.y;  nb.y = c*b.y + ss*a.x;
    a = na; b = nb;
}
__device__ __forceinline__ unsigned insert1(unsigned i, int h) {
    return ((i >> h) << (h + 1)) | (i & ((1u << h) - 1u));
}
__device__ __forceinline__ unsigned insert2(unsigned i, int lo, int hi) {
    unsigned p = ((i >> lo) << (lo + 1)) | (i & ((1u << lo) - 1u));
    p = ((p >> hi) << (hi + 1)) | (p & ((1u << hi) - 1u));
    return p;
}
__device__ __forceinline__ int par(unsigned x) { return __popc(x) & 1; }

// ---- local 1q stage over the 11-bit half space ----
__device__ void stage_1q(float2 (*gt)[4], const Plan& PL, int blk,
                         float2* amp, const float2* peer,
                         unsigned rank, int t, cg::cluster_group& cl)
{
    const int nl = PL.n1loc[blk];
    // local quads
    for (int g = 0; g + 1 < nl; g += 2) {
        const int qA = PL.ord1[blk][g], qB = PL.ord1[blk][g+1];
        const unsigned mA = PL.m1[blk][qA], RA = PL.R1[blk][qA];
        const unsigned mB = PL.m1[blk][qB], RB = PL.R1[blk][qB];
        const int hA = 31 - __clz((int)mA), hB = 31 - __clz((int)mB);
        const int lo = hA < hB ? hA : hB, hi = hA < hB ? hB : hA;
        float2 gA[4], gB[4];
#pragma unroll
        for (int k = 0; k < 4; k++) { gA[k] = gt[qA][k]; gB[k] = gt[qB][k]; }
        unsigned p = insert2((unsigned)t, lo, hi);
        unsigned base = p;
        if (par(p & RA & 0x7FFu) ^ (rank & (RA >> 11))) base ^= mA;
        if (par(p & RB & 0x7FFu) ^ (rank & (RB >> 11))) base ^= mB;
        const unsigned i10 = base ^ mA, i01 = base ^ mB, i11 = base ^ mA ^ mB;
        float2 a00 = amp[base], a10 = amp[i10], a01 = amp[i01], a11 = amp[i11];
        apply2(gA, a00, a10); apply2(gA, a01, a11);
        apply2(gB, a00, a01); apply2(gB, a10, a11);
        amp[base] = a00; amp[i10] = a10; amp[i01] = a01; amp[i11] = a11;
        __syncthreads();
    }
    // leftover single local gate
    if (nl & 1) {
        const int q = PL.ord1[blk][nl-1];
        const unsigned m = PL.m1[blk][q], R = PL.R1[blk][q];
        const int h = 31 - __clz((int)m);
        float2 g[4];
#pragma unroll
        for (int k = 0; k < 4; k++) g[k] = gt[q][k];
#pragma unroll
        for (int k = 0; k < 2; k++) {
            unsigned p = insert1((unsigned)(t + k*NT), h);
            unsigned base = p;
            if (par(p & R & 0x7FFu) ^ (rank & (R >> 11))) base ^= m;
            unsigned i1 = base ^ m;
            float2 a0 = amp[base], a1 = amp[i1];
            apply2(g, a0, a1);
            amp[base] = a0; amp[i1] = a1;
        }
        __syncthreads();
    }
    // cross gates (element-local, DSMEM partner)
    for (int c = nl; c < NQ; c++) {
        const int q = PL.ord1[blk][c];
        const unsigned m = PL.m1[blk][q], R = PL.R1[blk][q];
        const unsigned mlow = m & 0x7FFu;
        float2 g[4];
#pragma unroll
        for (int k = 0; k < 4; k++) g[k] = gt[q][k];
        cl.sync();
        float2 pv[4];
#pragma unroll
        for (int j = 0; j < 4; j++) {
            unsigned l = (unsigned)t + j*NT;
            pv[j] = peer[l ^ mlow];
        }
        cl.sync();
#pragma unroll
        for (int j = 0; j < 4; j++) {
            unsigned l = (unsigned)t + j*NT;
            int lb = par(l & R & 0x7FFu) ^ (rank & (R >> 11));
            float2 cA = lb ? g[3] : g[0];
            float2 cB = lb ? g[2] : g[1];
            float2 a = amp[l];
            float2 r;
            r.x = cA.x*a.x - cA.y*a.y + cB.x*pv[j].x - cB.y*pv[j].y;
            r.y = cA.x*a.y + cA.y*a.x + cB.x*pv[j].y + cB.y*pv[j].x;
            amp[l] = r;
        }
        __syncthreads();
    }
}

__global__ void __launch_bounds__(NT, 1) __cluster_dims__(2, 1, 1)
qsim_kernel(const float* __restrict__ data,
            const float* __restrict__ es,
            const float* __restrict__ eb,
            const float* __restrict__ eta,
            const float* __restrict__ ew_zz,
            const float* __restrict__ ew_xx,
            const float* __restrict__ ew_yy,
            const float* __restrict__ nb_z,
            const float* __restrict__ nb_x,
            const float* __restrict__ nb_y,
            const float* __restrict__ rots,
            Plan PL,
            float* __restrict__ out)
{
    __shared__ float2 amp[HDIM];
    __shared__ float2 gT1[NQ][4];
    __shared__ float2 gT2[NQ][4];
    __shared__ float  sC[NQ], sS[NQ], sH[NQ];
    __shared__ float  red[NT/32][NQ];
    __shared__ float  sums[NQ];

    cg::cluster_group cl = cg::this_cluster();
    const unsigned rank = blockIdx.x & 1u;
    const int b = blockIdx.x >> 1;
    const int t = threadIdx.x;
    float2* peer = cl.map_shared_rank(amp, rank ^ 1u);
    float*  psums = cl.map_shared_rank(sums, 1u);

#pragma unroll
    for (int j = 0; j < 4; j++) {
        int l = t + j*NT;
        amp[l] = make_float2((l == 0 && rank == 0) ? 1.0f : 0.0f, 0.0f);
    }

    for (int blk = 0; blk < 3; blk++) {
        if (t < NQ) {
            const int q = t;
            float d  = data[b*NQ + q];
            float ax = es[q*3+0]*d + eb[q*3+0];
            float ay = es[q*3+1]*d + eb[q*3+1];
            float az = es[q*3+2]*d + eb[q*3+2];
            CM M;
            if (blk == 0)      M = mm(RZ(az), mm(RY(ay), RX(ax)));
            else if (blk == 1) M = mm(RY(ay), RX(ax));
            else               M = mm(RZ(az), RY(ay));
#pragma unroll
            for (int k = 0; k < 4; k++) gT1[q][k] = M.m[k];

            float bias = (blk == 0) ? nb_z[q] : (blk == 1) ? nb_x[q] : nb_y[q];
            CM Mb = (blk == 0) ? RZ(bias) : (blk == 1) ? RX(bias) : RY(bias);
            const float* rr = rots + blk*(NQ*3) + q*3;
            CM M2 = mm(RZ(rr[2]), mm(RY(rr[1]), mm(RX(rr[0]), Mb)));
#pragma unroll
            for (int k = 0; k < 4; k++) gT2[q][k] = M2.m[k];

            float ew = (blk == 0) ? ew_zz[q] : (blk == 1) ? ew_xx[q] : ew_yy[q];
            float h = 0.5f * eta[blk] * ew;
            float s, c; sincosf(h, &s, &c);
            sC[q] = c; sS[q] = s; sH[q] = h;
        }
        __syncthreads();

        // ---- encoding 1q stage ----
        stage_1q(gT1, PL, blk, amp, peer, rank, t, cl);

        // ---- Ising ----
        if (blk == 0) {
            float h[NQ]; unsigned short X[NQ];
#pragma unroll
            for (int e = 0; e < NQ; e++) { h[e] = sH[e]; X[e] = PL.XE[0][e]; }
#pragma unroll
            for (int j = 0; j < 4; j++) {
                unsigned l = (unsigned)t + j*NT;
                float phi = 0.0f;
#pragma unroll
                for (int e = 0; e < NQ; e++) {
                    int sgn = par(l & X[e] & 0x7FFu) ^ (rank & (X[e] >> 11));
                    phi += sgn ? h[e] : -h[e];
                }
                float sp, cp; __sincosf(phi, &sp, &cp);
                float2 a = amp[l];
                amp[l] = make_float2(a.x*cp - a.y*sp, a.x*sp + a.y*cp);
            }
            __syncthreads();
        } else {
            const int nE = PL.nEloc[blk];
            // local quad-mix sweeps
            for (int g = 0; g + 1 < nE; g += 2) {
                const int e1 = PL.ordE[blk][g], e2 = PL.ordE[blk][g+1];
                const unsigned m1 = PL.mE[blk][e1], m2 = PL.mE[blk][e2];
                const float c1 = sC[e1], s1 = sS[e1];
                const float c2 = sC[e2], s2 = sS[e2];
                const int h1 = 31 - __clz((int)m1), h2 = 31 - __clz((int)m2);
                const int lo = h1 < h2 ? h1 : h2, hi = h1 < h2 ? h2 : h1;
                unsigned p = insert2((unsigned)t, lo, hi);
                const unsigned iA = p ^ m1, iB = p ^ m2, iC = p ^ m1 ^ m2;
                float2 r0 = amp[p], r1 = amp[iA], r2 = amp[iB], r3 = amp[iC];
                if (blk == 1) {
                    applyMix(c1, -s1, r0, r1); applyMix(c1, -s1, r2, r3);
                    applyMix(c2, -s2, r0, r2); applyMix(c2, -s2, r1, r3);
                } else {
                    const unsigned X1 = PL.XE[2][e1], X2 = PL.XE[2][e2];
                    const unsigned adj1 = par(m2 & X1 & 0x7FFu);
                    const unsigned adj2 = par(m1 & X2 & 0x7FFu);
                    unsigned t1 = par(p & X1 & 0x7FFu) ^ (rank & (X1 >> 11));
                    applyMix(c1, t1 ? -s1 : s1, r0, r1);
                    applyMix(c1, (t1 ^ adj1) ? -s1 : s1, r2, r3);
                    unsigned t2 = par(p & X2 & 0x7FFu) ^ (rank & (X2 >> 11));
                    applyMix(c2, t2 ? -s2 : s2, r0, r2);
                    applyMix(c2, (t2 ^ adj2) ? -s2 : s2, r1, r3);
                }
                amp[p] = r0; amp[iA] = r1; amp[iB] = r2; amp[iC] = r3;
                __syncthreads();
            }
            // leftover single local edge (defensive; normally nE even)
            int c = nE;
            if (nE & 1) {
                const int e1 = PL.ordE[blk][nE-1];
                const unsigned m = PL.mE[blk][e1];
                const float cc = sC[e1], ssv = sS[e1];
                const int h = 31 - __clz((int)m);
                const unsigned X1 = PL.XE[2][e1];
#pragma unroll
                for (int k = 0; k < 2; k++) {
                    unsigned p = insert1((unsigned)(t + k*NT), h);
                    unsigned j1 = p ^ m;
                    float2 a0 = amp[p], a1 = amp[j1];
                    float ss;
                    if (blk == 1) ss = -ssv;
                    else {
                        unsigned t1 = par(p & X1 & 0x7FFu) ^ (rank & (X1 >> 11));
                        ss = t1 ? -ssv : ssv;
                    }
                    applyMix(cc, ss, a0, a1);
                    amp[p] = a0; amp[j1] = a1;
                }
                __syncthreads();
            }
            // cross edges
            while (c + 1 < NQ) {
                const int e1 = PL.ordE[blk][c], e2 = PL.ordE[blk][c+1];
                const unsigned m1 = PL.mE[blk][e1], m2 = PL.mE[blk][e2];
                const unsigned m12 = (m1 ^ m2) & 0xFFFu;   // local mask
                const float c1 = sC[e1], s1 = sS[e1];
                const float c2 = sC[e2], s2 = sS[e2];
                const float cc = c1 * c2;
                const unsigned X1 = (blk == 2) ? PL.XE[2][e1] : 0u;
                const unsigned X2 = (blk == 2) ? PL.XE[2][e2] : 0u;
                const int f1 = (blk == 2) ? par(m2 & X1 & 0xFFFu) : 0;
                cl.sync();
                float2 A[4], P1[4], P2[4], P12[4];
#pragma unroll
                for (int j = 0; j < 4; j++) {
                    unsigned l = (unsigned)t + j*NT;
                    A[j]   = amp[l];
                    P1[j]  = peer[l ^ (m1 & 0x7FFu)];
                    P2[j]  = peer[l ^ (m2 & 0x7FFu)];
                    P12[j] = amp[l ^ m12];
                }
                cl.sync();
#pragma unroll
                for (int j = 0; j < 4; j++) {
                    unsigned l = (unsigned)t + j*NT;
                    float w1, w2;
                    if (blk == 1) { w1 = -s1; w2 = -s2; }
                    else {
                        int p1 = par(l & X1 & 0x7FFu) ^ (rank & (X1 >> 11));
                        int p2 = par(l & X2 & 0x7FFu) ^ (rank & (X2 >> 11));
                        w1 = p1 ? -s1 : s1;
                        w2 = p2 ? -s2 : s2;
                    }
                    float w1p = f1 ? -w1 : w1;
                    float T4  = -(w2 * w1p);
                    float k1 = c2 * w1, k2 = c1 * w2;
                    float2 r;
                    r.x = cc*A[j].x - k1*P1[j].y - k2*P2[j].y + T4*P12[j].x;
                    r.y = cc*A[j].y + k1*P1[j].x + k2*P2[j].x + T4*P12[j].y;
                    amp[l] = r;
                }
                __syncthreads();
                c += 2;
            }
            if (c < NQ) {   // single cross edge (defensive)
                const int e1 = PL.ordE[blk][c];
                const unsigned m = PL.mE[blk][e1];
                const float c1 = sC[e1], s1 = sS[e1];
                const unsigned X1 = (blk == 2) ? PL.XE[2][e1] : 0u;
                cl.sync();
                float2 pv[4];
#pragma unroll
                for (int j = 0; j < 4; j++) {
                    unsigned l = (unsigned)t + j*NT;
                    pv[j] = peer[l ^ (m & 0x7FFu)];
                }
                cl.sync();
#pragma unroll
                for (int j = 0; j < 4; j++) {
                    unsigned l = (unsigned)t + j*NT;
                    float w1;
                    if (blk == 1) w1 = -s1;
                    else {
                        int p1 = par(l & X1 & 0x7FFu) ^ (rank & (X1 >> 11));
                        w1 = p1 ? -s1 : s1;
                    }
                    float2 a = amp[l];
                    float2 r;
                    r.x = c1*a.x - w1*pv[j].y;
                    r.y = c1*a.y + w1*pv[j].x;
                    amp[l] = r;
                }
                __syncthreads();
            }
        }

        // ---- bias + trainable rots ----
        stage_1q(gT2, PL, blk, amp, peer, rank, t, cl);
    }

    // ---- measurement over local half ----
    float acc[NQ];
#pragma unroll
    for (int i = 0; i < NQ; i++) acc[i] = 0.0f;
#pragma unroll
    for (int j = 0; j < 4; j++) {
        unsigned l = (unsigned)t + j*NT;
        float2 a = amp[l];
        float pr = a.x*a.x + a.y*a.y;
#pragma unroll
        for (int i = 0; i < NQ; i++) {
            unsigned Rm = PL.RM[i];
            int sg = par(l & Rm & 0x7FFu) ^ (rank & (Rm >> 11));
            acc[i] += sg ? -pr : pr;
        }
    }
#pragma unroll
    for (int off = 16; off > 0; off >>= 1)
#pragma unroll
        for (int i = 0; i < NQ; i++)
            acc[i] += __shfl_down_sync(0xffffffffu, acc[i], off);
    const int wid = t >> 5;
    if ((t & 31) == 0) {
#pragma unroll
        for (int i = 0; i < NQ; i++) red[wid][i] = acc[i];
    }
    __syncthreads();
    if (t < NQ) {
        float s = 0.0f;
#pragma unroll
        for (int w = 0; w < NT/32; w++) s += red[w][t];
        sums[t] = s;
    }
    __syncthreads();
    cl.sync();
    if (rank == 0 && t < NQ)
        out[b*NQ + t] = sums[t] + psums[t];
    cl.sync();
}

// ---- host: GF(2) algebra of the CNOT ring ----
static inline unsigned Gm(unsigned j) {
    unsigned r = (j ^ (j >> 1)) & 0xFFFu;
    r ^= (j >> 11) & 1u;
    return r;
}
static inline unsigned Fm(unsigned k) {
    unsigned p = k;
    p ^= p >> 1; p ^= p >> 2; p ^= p >> 4; p ^= p >> 8;
    p &= 0xFFFu;
    return (p & 0xFFEu) | ((p ^ (k >> 11)) & 1u);
}

extern "C" void kernel_launch(void* const* d_in, const int* in_sizes, int n_in,
                              void* d_out, int out_size) {
    const float* data   = (const float*)d_in[0];
    const float* es     = (const float*)d_in[1];
    const float* eb     = (const float*)d_in[2];
    const float* eta    = (const float*)d_in[3];
    const float* ew_zz  = (const float*)d_in[4];
    const float* ew_xx  = (const float*)d_in[5];
    const float* ew_yy  = (const float*)d_in[6];
    const float* nb_z   = (const float*)d_in[7];
    const float* nb_x   = (const float*)d_in[8];
    const float* nb_y   = (const float*)d_in[9];
    const float* rots   = (const float*)d_in[10];
    float* out = (float*)d_out;

    Plan PL;
    unsigned rows[4][12];
    for (int p = 0; p < 4; p++) {
        unsigned col[12];
        for (int j = 0; j < 12; j++) {
            unsigned v = 1u << j;
            for (int it = 0; it < p; it++) v = Fm(v);
            col[j] = v;
        }
        for (int q = 0; q < 12; q++) {
            unsigned r = 0;
            for (int j = 0; j < 12; j++) r |= ((col[j] >> q) & 1u) << j;
            rows[p][q] = r;
        }
    }
    for (int blk = 0; blk < 3; blk++) {
        for (int q = 0; q < 12; q++) {
            unsigned m = 1u << q;
            for (int it = 0; it < blk; it++) m = Gm(m);
            PL.m1[blk][q] = (unsigned short)m;
            PL.R1[blk][q] = (unsigned short)rows[blk][q];
        }
        for (int e = 0; e < 12; e++) {
            unsigned a  = (e < 11) ? (unsigned)(11 - e) : 11u;
            unsigned b2 = (e < 11) ? (unsigned)(10 - e) : 0u;
            unsigned M = (1u << a) | (1u << b2);
            unsigned m = M;
            for (int it = 0; it < blk; it++) m = Gm(m);
            PL.mE[blk][e] = (unsigned short)m;
            PL.XE[blk][e] = (unsigned short)(rows[blk][a] ^ rows[blk][b2]);
        }
        // locals-first orderings
        int nl = 0, nc = 0;
        unsigned char tmp1[12];
        for (int q = 0; q < 12; q++) {
            if (PL.m1[blk][q] & 0x800) tmp1[11 - (nc++)] = (unsigned char)q;
            else                        tmp1[nl++]        = (unsigned char)q;
        }
        PL.n1loc[blk] = nl;
        for (int q = 0; q < 12; q++) PL.ord1[blk][q] = tmp1[q];

        nl = 0; nc = 0;
        unsigned char tmpE[12];
        for (int e = 0; e < 12; e++) {
            if (PL.mE[blk][e] & 0x800) tmpE[11 - (nc++)] = (unsigned char)e;
            else                        tmpE[nl++]        = (unsigned char)e;
        }
        PL.nEloc[blk] = nl;
        for (int e = 0; e < 12; e++) PL.ordE[blk][e] = tmpE[e];
    }
    for (int i = 0; i < 12; i++) PL.RM[i] = (unsigned short)rows[3][11 - i];

    int B = in_sizes[0] / NQ;   // 64
    qsim_kernel<<<B * 2, NT>>>(data, es, eb, eta, ew_zz, ew_xx, ew_yy,
                               nb_z, nb_x, nb_y, rots, PL, out);
}

// round 4
// speedup vs baseline: 1.9266x; 1.2572x over previous
#include <cuda_runtime.h>
#include <cooperative_groups.h>
namespace cg = cooperative_groups;

#define NQ    12
#define HDIM  2048      // per-CTA half state
#define NT    512

struct Plan {
    unsigned short m1[3][NQ], R1[3][NQ];   // 1q pair masks / sign rows (12-bit)
    unsigned short mE[3][NQ], XE[3][NQ];   // edge pair masks / sign rows
    unsigned short RM[NQ];                 // measurement rows
};

struct CM { float2 m[4]; };

__device__ __forceinline__ float2 cxmul(float2 a, float2 b) {
    return make_float2(a.x*b.x - a.y*b.y, a.x*b.y + a.y*b.x);
}
__device__ __forceinline__ float2 cxadd(float2 a, float2 b) {
    return make_float2(a.x + b.x, a.y + b.y);
}
__device__ __forceinline__ CM mm(const CM& A, const CM& B) {
    CM C;
#pragma unroll
    for (int i = 0; i < 2; i++)
#pragma unroll
        for (int j = 0; j < 2; j++)
            C.m[i*2+j] = cxadd(cxmul(A.m[i*2+0], B.m[0*2+j]),
                               cxmul(A.m[i*2+1], B.m[1*2+j]));
    return C;
}
__device__ __forceinline__ CM RX(float t) {
    float s, c; sincosf(0.5f*t, &s, &c);
    CM M;
    M.m[0] = make_float2(c,0.f);  M.m[1] = make_float2(0.f,-s);
    M.m[2] = make_float2(0.f,-s); M.m[3] = make_float2(c,0.f);
    return M;
}
__device__ __forceinline__ CM RY(float t) {
    float s, c; sincosf(0.5f*t, &s, &c);
    CM M;
    M.m[0] = make_float2(c,0.f); M.m[1] = make_float2(-s,0.f);
    M.m[2] = make_float2(s,0.f); M.m[3] = make_float2(c,0.f);
    return M;
}
__device__ __forceinline__ CM RZ(float t) {
    float s, c; sincosf(0.5f*t, &s, &c);
    CM M;
    M.m[0] = make_float2(c,-s);    M.m[1] = make_float2(0.f,0.f);
    M.m[2] = make_float2(0.f,0.f); M.m[3] = make_float2(c,s);
    return M;
}

__device__ __forceinline__ void apply2(const float2 g[4], float2 &a0, float2 &a1) {
    float2 n0, n1;
    n0.x = g[0].x*a0.x - g[0].y*a0.y + g[1].x*a1.x - g[1].y*a1.y;
    n0.y = g[0].x*a0.y + g[0].y*a0.x + g[1].x*a1.y + g[1].y*a1.x;
    n1.x = g[2].x*a0.x - g[2].y*a0.y + g[3].x*a1.x - g[3].y*a1.y;
    n1.y = g[2].x*a0.y + g[2].y*a0.x + g[3].x*a1.y + g[3].y*a1.x;
    a0 = n0; a1 = n1;
}
__device__ __forceinline__ void applyMix(float c, float ss, float2 &a, float2 &b) {
    float2 na, nb;
    na.x = c*a.x - ss*b.y;  na.y = c*a.y + ss*b.x;
    nb.x = c*b.x - ss*a.y;  nb.y = c*b.y + ss*a.x;
    a = na; b = nb;
}
__device__ __forceinline__ unsigned insert1(unsigned i, int h) {
    return ((i >> h) << (h + 1)) | (i & ((1u << h) - 1u));
}
__device__ __forceinline__ unsigned insert2(unsigned i, int lo, int hi) {
    unsigned p = ((i >> lo) << (lo + 1)) | (i & ((1u << lo) - 1u));
    p = ((p >> hi) << (hi + 1)) | (p & ((1u << hi) - 1u));
    return p;
}
__device__ __forceinline__ int par(unsigned x) { return __popc(x) & 1; }
__device__ __forceinline__ void cfma(float2& acc, float2 a, float2 b) {
    acc.x += a.x*b.x - a.y*b.y;
    acc.y += a.x*b.y + a.y*b.x;
}

__global__ void __launch_bounds__(NT, 1) __cluster_dims__(2, 1, 1)
qsim_kernel(const float* __restrict__ data,
            const float* __restrict__ es,
            const float* __restrict__ eb,
            const float* __restrict__ eta,
            const float* __restrict__ ew_zz,
            const float* __restrict__ ew_xx,
            const float* __restrict__ ew_yy,
            const float* __restrict__ nb_z,
            const float* __restrict__ nb_x,
            const float* __restrict__ nb_y,
            const float* __restrict__ rots,
            Plan PL,
            float* __restrict__ out)
{
    __shared__ float2 amp[HDIM];
    __shared__ float2 gT1[NQ][4];
    __shared__ float2 gT2[NQ][4];
    __shared__ float2 gX[2][4];        // deferred bias q11 gate, double-buffered by block parity
    __shared__ float  sC[NQ], sS[NQ], sH[NQ];
    __shared__ float  red[NT/32][NQ];
    __shared__ float  sums[NQ];

    cg::cluster_group cl = cg::this_cluster();
    const unsigned rank = blockIdx.x & 1u;
    const int b = blockIdx.x >> 1;
    const int t = threadIdx.x;
    float2* peer = cl.map_shared_rank(amp, rank ^ 1u);
    float*  psums = cl.map_shared_rank(sums, 1u);

    for (int blk = 0; blk < 3; blk++) {
        // ---- per-block gate tables (threads 0..11) ----
        if (t < NQ) {
            const int q = t;
            float d  = data[b*NQ + q];
            float ax = es[q*3+0]*d + eb[q*3+0];
            float ay = es[q*3+1]*d + eb[q*3+1];
            float az = es[q*3+2]*d + eb[q*3+2];
            CM M;
            if (blk == 0)      M = mm(RZ(az), mm(RY(ay), RX(ax)));
            else if (blk == 1) M = mm(RY(ay), RX(ax));
            else               M = mm(RZ(az), RY(ay));
#pragma unroll
            for (int k = 0; k < 4; k++) gT1[q][k] = M.m[k];

            float bias = (blk == 0) ? nb_z[q] : (blk == 1) ? nb_x[q] : nb_y[q];
            CM Mb = (blk == 0) ? RZ(bias) : (blk == 1) ? RX(bias) : RY(bias);
            const float* rr = rots + blk*(NQ*3) + q*3;
            CM M2 = mm(RZ(rr[2]), mm(RY(rr[1]), mm(RX(rr[0]), Mb)));
#pragma unroll
            for (int k = 0; k < 4; k++) gT2[q][k] = M2.m[k];
            if (q == 11) {
#pragma unroll
                for (int k = 0; k < 4; k++) gX[blk & 1][k] = M2.m[k];
            }

            float ew = (blk == 0) ? ew_zz[q] : (blk == 1) ? ew_xx[q] : ew_yy[q];
            float h = 0.5f * eta[blk] * ew;
            float s, c; sincosf(h, &s, &c);
            sC[q] = c; sS[q] = s; sH[q] = h;
        }
        __syncthreads();

        if (blk == 0) {
            // ---- product-state init (full encoding stage on |0..0>) + fused ZZ phase ----
            float2 prod = rank ? gT1[11][2] : gT1[11][0];
#pragma unroll
            for (int q = 0; q < 9; q++) {
                float2 f = ((t >> q) & 1) ? gT1[q][2] : gT1[q][0];
                prod = cxmul(prod, f);
            }
#pragma unroll
            for (int j = 0; j < 4; j++) {
                unsigned l = (unsigned)t + j*NT;
                float2 v = cxmul(prod, (j & 1) ? gT1[9][2]  : gT1[9][0]);
                v = cxmul(v,           (j & 2) ? gT1[10][2] : gT1[10][0]);
                unsigned k12 = l | (rank << 11);
                float phi = 0.0f;
#pragma unroll
                for (int e = 0; e < NQ; e++)
                    phi += par(k12 & PL.XE[0][e]) ? sH[e] : -sH[e];
                float sp, cp; __sincosf(phi, &sp, &cp);
                amp[l] = make_float2(v.x*cp - v.y*sp, v.x*sp + v.y*cp);
            }
            __syncthreads();
        } else {
            // ---- fused cross exchange: bias(blk-1)@q11 then enc(blk)@q11 ----
            // Both sign rows are 0x800 -> parity == rank -> uniform coefficients.
            const unsigned ma = PL.m1[blk-1][11], mb = PL.m1[blk][11];
            float2 ga[4], gb[4];
#pragma unroll
            for (int k = 0; k < 4; k++) { ga[k] = gX[(blk-1) & 1][k]; gb[k] = gT1[11][k]; }
            const float2 ga_d  = rank ? ga[3] : ga[0];
            const float2 ga_o  = rank ? ga[2] : ga[1];
            const float2 ga_d2 = rank ? ga[0] : ga[3];
            const float2 ga_o2 = rank ? ga[1] : ga[2];
            const float2 gb_d  = rank ? gb[3] : gb[0];
            const float2 gb_o  = rank ? gb[2] : gb[1];
            const float2 C1 = cxmul(gb_d, ga_d);
            const float2 C2 = cxmul(gb_d, ga_o);
            const float2 C3 = cxmul(gb_o, ga_d2);
            const float2 C4 = cxmul(gb_o, ga_o2);
            const unsigned m12 = (ma ^ mb) & 0x7FFu;
            const int h12 = 31 - __clz((int)m12);
            const unsigned pa = ma & 0x7FFu, pb = mb & 0x7FFu;
            cl.sync();
            float2 r0[2], r1[2], q0[2], q1[2];
#pragma unroll
            for (int j = 0; j < 2; j++) {
                unsigned base = insert1((unsigned)(t + j*NT), h12);
                r0[j] = amp[base];       r1[j] = amp[base ^ m12];
                q0[j] = peer[base ^ pa]; q1[j] = peer[base ^ pb];
            }
            cl.sync();
#pragma unroll
            for (int j = 0; j < 2; j++) {
                unsigned base = insert1((unsigned)(t + j*NT), h12);
                float2 o0 = make_float2(0.f, 0.f), o1 = make_float2(0.f, 0.f);
                cfma(o0, C1, r0[j]); cfma(o0, C2, q0[j]);
                cfma(o0, C3, q1[j]); cfma(o0, C4, r1[j]);
                cfma(o1, C1, r1[j]); cfma(o1, C2, q1[j]);
                cfma(o1, C3, q0[j]); cfma(o1, C4, r0[j]);
                amp[base] = o0; amp[base ^ m12] = o1;
            }
            __syncthreads();

            // ---- encoding locals (q = 0..10), 5 quads + 1 single ----
            for (int g = 0; g < 5; g++) {
                const int qA = 2*g, qB = 2*g + 1;
                const unsigned mA = PL.m1[blk][qA], RA = PL.R1[blk][qA];
                const unsigned mB = PL.m1[blk][qB], RB = PL.R1[blk][qB];
                const int hA = 31 - __clz((int)mA), hB = 31 - __clz((int)mB);
                const int lo = hA < hB ? hA : hB, hi = hA < hB ? hB : hA;
                float2 gA[4], gB[4];
#pragma unroll
                for (int k = 0; k < 4; k++) { gA[k] = gT1[qA][k]; gB[k] = gT1[qB][k]; }
                unsigned p = insert2((unsigned)t, lo, hi);
                unsigned base = p;
                if (par(p & RA & 0x7FFu) ^ (rank & (RA >> 11))) base ^= mA;
                if (par(p & RB & 0x7FFu) ^ (rank & (RB >> 11))) base ^= mB;
                const unsigned i10 = base ^ mA, i01 = base ^ mB, i11 = base ^ mA ^ mB;
                float2 a00 = amp[base], a10 = amp[i10], a01 = amp[i01], a11 = amp[i11];
                apply2(gA, a00, a10); apply2(gA, a01, a11);
                apply2(gB, a00, a01); apply2(gB, a10, a11);
                amp[base] = a00; amp[i10] = a10; amp[i01] = a01; amp[i11] = a11;
                __syncthreads();
            }
            {
                const int q = 10;
                const unsigned m = PL.m1[blk][q], R = PL.R1[blk][q];
                const int h = 31 - __clz((int)m);
                float2 g[4];
#pragma unroll
                for (int k = 0; k < 4; k++) g[k] = gT1[q][k];
#pragma unroll
                for (int k = 0; k < 2; k++) {
                    unsigned p = insert1((unsigned)(t + k*NT), h);
                    unsigned base = p;
                    if (par(p & R & 0x7FFu) ^ (rank & (R >> 11))) base ^= m;
                    unsigned i1 = base ^ m;
                    float2 a0 = amp[base], a1 = amp[i1];
                    apply2(g, a0, a1);
                    amp[base] = a0; amp[i1] = a1;
                }
                __syncthreads();
            }

            // ---- Ising edges: locals e=1..10 (5 quads), then cross pair (e=11, e=0) ----
            for (int g = 0; g < 5; g++) {
                const int e1 = 2*g + 1, e2 = 2*g + 2;
                const unsigned m1 = PL.mE[blk][e1], m2 = PL.mE[blk][e2];
                const float c1 = sC[e1], s1 = sS[e1];
                const float c2 = sC[e2], s2 = sS[e2];
                const int h1 = 31 - __clz((int)m1), h2 = 31 - __clz((int)m2);
                const int lo = h1 < h2 ? h1 : h2, hi = h1 < h2 ? h2 : h1;
                unsigned p = insert2((unsigned)t, lo, hi);
                const unsigned iA = p ^ m1, iB = p ^ m2, iC = p ^ m1 ^ m2;
                float2 r0 = amp[p], r1 = amp[iA], r2 = amp[iB], r3 = amp[iC];
                if (blk == 1) {
                    applyMix(c1, -s1, r0, r1); applyMix(c1, -s1, r2, r3);
                    applyMix(c2, -s2, r0, r2); applyMix(c2, -s2, r1, r3);
                } else {
                    const unsigned X1 = PL.XE[2][e1], X2 = PL.XE[2][e2];
                    const unsigned adj1 = par(m2 & X1 & 0x7FFu);
                    const unsigned adj2 = par(m1 & X2 & 0x7FFu);
                    unsigned t1 = par(p & X1 & 0x7FFu) ^ (rank & (X1 >> 11));
                    applyMix(c1, t1 ? -s1 : s1, r0, r1);
                    applyMix(c1, (t1 ^ adj1) ? -s1 : s1, r2, r3);
                    unsigned t2 = par(p & X2 & 0x7FFu) ^ (rank & (X2 >> 11));
                    applyMix(c2, t2 ? -s2 : s2, r0, r2);
                    applyMix(c2, (t2 ^ adj2) ? -s2 : s2, r1, r3);
                }
                amp[p] = r0; amp[iA] = r1; amp[iB] = r2; amp[iC] = r3;
                __syncthreads();
            }
            {
                // cross pair, pair-based (thread owns {base, base^m12})
                const int e1 = 11, e2 = 0;
                const unsigned m1e = PL.mE[blk][e1], m2e = PL.mE[blk][e2];
                const float c1 = sC[e1], s1 = sS[e1];
                const float c2 = sC[e2], s2 = sS[e2];
                const float cc = c1 * c2;
                const unsigned X1 = PL.XE[2][e1], X2 = PL.XE[2][e2];
                const int f1 = (blk == 2) ? par(m2e & X1 & 0xFFFu) : 0;
                const unsigned m12 = (m1e ^ m2e) & 0x7FFu;
                const int h12 = 31 - __clz((int)m12);
                const unsigned p1m = m1e & 0x7FFu, p2m = m2e & 0x7FFu;
                cl.sync();
                float2 A0[2], A1[2], P1[2], P2[2];
#pragma unroll
                for (int j = 0; j < 2; j++) {
                    unsigned base = insert1((unsigned)(t + j*NT), h12);
                    A0[j] = amp[base];        A1[j] = amp[base ^ m12];
                    P1[j] = peer[base ^ p1m]; P2[j] = peer[base ^ p2m];
                }
                cl.sync();
#pragma unroll
                for (int j = 0; j < 2; j++) {
                    unsigned base = insert1((unsigned)(t + j*NT), h12);
                    float w1, w2, w1b, w2b;
                    if (blk == 1) { w1 = -s1; w2 = -s2; w1b = w1; w2b = w2; }
                    else {
                        unsigned k12  = base | (rank << 11);
                        unsigned k12b = k12 ^ m12;
                        w1  = par(k12  & X1) ? -s1 : s1;
                        w2  = par(k12  & X2) ? -s2 : s2;
                        w1b = par(k12b & X1) ? -s1 : s1;
                        w2b = par(k12b & X2) ? -s2 : s2;
                    }
                    {
                        float w1p = f1 ? -w1 : w1;
                        float T4 = -(w2 * w1p);
                        float k1 = c2 * w1, k2 = c1 * w2;
                        float2 r;
                        r.x = cc*A0[j].x - k1*P1[j].y - k2*P2[j].y + T4*A1[j].x;
                        r.y = cc*A0[j].y + k1*P1[j].x + k2*P2[j].x + T4*A1[j].y;
                        amp[base] = r;
                    }
                    {
                        float w1p = f1 ? -w1b : w1b;
                        float T4 = -(w2b * w1p);
                        float k1 = c2 * w1b, k2 = c1 * w2b;
                        float2 r;
                        r.x = cc*A1[j].x - k1*P2[j].y - k2*P1[j].y + T4*A0[j].x;
                        r.y = cc*A1[j].y + k1*P2[j].x + k2*P1[j].x + T4*A0[j].y;
                        amp[base ^ m12] = r;
                    }
                }
                __syncthreads();
            }
        }

        // ---- bias + trainable rots locals (q = 0..10); q11 deferred to next block ----
        for (int g = 0; g < 5; g++) {
            const int qA = 2*g, qB = 2*g + 1;
            const unsigned mA = PL.m1[blk][qA], RA = PL.R1[blk][qA];
            const unsigned mB = PL.m1[blk][qB], RB = PL.R1[blk][qB];
            const int hA = 31 - __clz((int)mA), hB = 31 - __clz((int)mB);
            const int lo = hA < hB ? hA : hB, hi = hA < hB ? hB : hA;
            float2 gA[4], gB[4];
#pragma unroll
            for (int k = 0; k < 4; k++) { gA[k] = gT2[qA][k]; gB[k] = gT2[qB][k]; }
            unsigned p = insert2((unsigned)t, lo, hi);
            unsigned base = p;
            if (par(p & RA & 0x7FFu) ^ (rank & (RA >> 11))) base ^= mA;
            if (par(p & RB & 0x7FFu) ^ (rank & (RB >> 11))) base ^= mB;
            const unsigned i10 = base ^ mA, i01 = base ^ mB, i11 = base ^ mA ^ mB;
            float2 a00 = amp[base], a10 = amp[i10], a01 = amp[i01], a11 = amp[i11];
            apply2(gA, a00, a10); apply2(gA, a01, a11);
            apply2(gB, a00, a01); apply2(gB, a10, a11);
            amp[base] = a00; amp[i10] = a10; amp[i01] = a01; amp[i11] = a11;
            __syncthreads();
        }
        {
            const int q = 10;
            const unsigned m = PL.m1[blk][q], R = PL.R1[blk][q];
            const int h = 31 - __clz((int)m);
            float2 g[4];
#pragma unroll
            for (int k = 0; k < 4; k++) g[k] = gT2[q][k];
#pragma unroll
            for (int k = 0; k < 2; k++) {
                unsigned p = insert1((unsigned)(t + k*NT), h);
                unsigned base = p;
                if (par(p & R & 0x7FFu) ^ (rank & (R >> 11))) base ^= m;
                unsigned i1 = base ^ m;
                float2 a0 = amp[base], a1 = amp[i1];
                apply2(g, a0, a1);
                amp[base] = a0; amp[i1] = a1;
            }
            __syncthreads();
        }
    }

    // ---- final deferred bias(blk2)@q11 cross (single gate) ----
    {
        const unsigned ma = PL.m1[2][11];
        float2 g[4];
#pragma unroll
        for (int k = 0; k < 4; k++) g[k] = gT2[11][k];
        const float2 gd = rank ? g[3] : g[0];
        const float2 go = rank ? g[2] : g[1];
        const unsigned pm = ma & 0x7FFu;
        cl.sync();
        float2 pv[4];
#pragma unroll
        for (int j = 0; j < 4; j++)
            pv[j] = peer[((unsigned)t + j*NT) ^ pm];
        cl.sync();
#pragma unroll
        for (int j = 0; j < 4; j++) {
            unsigned l = (unsigned)t + j*NT;
            float2 a = amp[l];
            float2 r;
            r.x = gd.x*a.x - gd.y*a.y + go.x*pv[j].x - go.y*pv[j].y;
            r.y = gd.x*a.y + gd.y*a.x + go.x*pv[j].y + go.y*pv[j].x;
            amp[l] = r;
        }
    }

    // ---- measurement over local half ----
    float acc[NQ];
#pragma unroll
    for (int i = 0; i < NQ; i++) acc[i] = 0.0f;
#pragma unroll
    for (int j = 0; j < 4; j++) {
        unsigned l = (unsigned)t + j*NT;
        float2 a = amp[l];
        float pr = a.x*a.x + a.y*a.y;
#pragma unroll
        for (int i = 0; i < NQ; i++) {
            unsigned Rm = PL.RM[i];
            int sg = par(l & Rm & 0x7FFu) ^ (rank & (Rm >> 11));
            acc[i] += sg ? -pr : pr;
        }
    }
#pragma unroll
    for (int off = 16; off > 0; off >>= 1)
#pragma unroll
        for (int i = 0; i < NQ; i++)
            acc[i] += __shfl_down_sync(0xffffffffu, acc[i], off);
    const int wid = t >> 5;
    if ((t & 31) == 0) {
#pragma unroll
        for (int i = 0; i < NQ; i++) red[wid][i] = acc[i];
    }
    __syncthreads();
    if (t < NQ) {
        float s = 0.0f;
#pragma unroll
        for (int w = 0; w < NT/32; w++) s += red[w][t];
        sums[t] = s;
    }
    __syncthreads();
    cl.sync();
    if (rank == 0 && t < NQ)
        out[b*NQ + t] = sums[t] + psums[t];
    cl.sync();
}

// ---- host: GF(2) algebra of the CNOT ring ----
static inline unsigned Gm(unsigned j) {
    unsigned r = (j ^ (j >> 1)) & 0xFFFu;
    r ^= (j >> 11) & 1u;
    return r;
}
static inline unsigned Fm(unsigned k) {
    unsigned p = k;
    p ^= p >> 1; p ^= p >> 2; p ^= p >> 4; p ^= p >> 8;
    p &= 0xFFFu;
    return (p & 0xFFEu) | ((p ^ (k >> 11)) & 1u);
}

extern "C" void kernel_launch(void* const* d_in, const int* in_sizes, int n_in,
                              void* d_out, int out_size) {
    const float* data   = (const float*)d_in[0];
    const float* es     = (const float*)d_in[1];
    const float* eb     = (const float*)d_in[2];
    const float* eta    = (const float*)d_in[3];
    const float* ew_zz  = (const float*)d_in[4];
    const float* ew_xx  = (const float*)d_in[5];
    const float* ew_yy  = (const float*)d_in[6];
    const float* nb_z   = (const float*)d_in[7];
    const float* nb_x   = (const float*)d_in[8];
    const float* nb_y   = (const float*)d_in[9];
    const float* rots   = (const float*)d_in[10];
    float* out = (float*)d_out;

    Plan PL;
    unsigned rows[4][12];
    for (int p = 0; p < 4; p++) {
        unsigned col[12];
        for (int j = 0; j < 12; j++) {
            unsigned v = 1u << j;
            for (int it = 0; it < p; it++) v = Fm(v);
            col[j] = v;
        }
        for (int q = 0; q < 12; q++) {
            unsigned r = 0;
            for (int j = 0; j < 12; j++) r |= ((col[j] >> q) & 1u) << j;
            rows[p][q] = r;
        }
    }
    for (int blk = 0; blk < 3; blk++) {
        for (int q = 0; q < 12; q++) {
            unsigned m = 1u << q;
            for (int it = 0; it < blk; it++) m = Gm(m);
            PL.m1[blk][q] = (unsigned short)m;
            PL.R1[blk][q] = (unsigned short)rows[blk][q];
        }
        for (int e = 0; e < 12; e++) {
            unsigned a  = (e < 11) ? (unsigned)(11 - e) : 11u;
            unsigned b2 = (e < 11) ? (unsigned)(10 - e) : 0u;
            unsigned M = (1u << a) | (1u << b2);
            unsigned m = M;
            for (int it = 0; it < blk; it++) m = Gm(m);
            PL.mE[blk][e] = (unsigned short)m;
            PL.XE[blk][e] = (unsigned short)(rows[blk][a] ^ rows[blk][b2]);
        }
    }
    for (int i = 0; i < 12; i++) PL.RM[i] = (unsigned short)rows[3][11 - i];

    int B = in_sizes[0] / NQ;   // 64
    qsim_kernel<<<B * 2, NT>>>(data, es, eb, eta, ew_zz, ew_xx, ew_yy,
                               nb_z, nb_x, nb_y, rots, PL, out);
}

// round 5
// speedup vs baseline: 2.0315x; 1.0544x over previous
#include <cuda_runtime.h>
#include <cooperative_groups.h>
namespace cg = cooperative_groups;

#define NQ    12
#define HDIM  2048      // per-CTA half state
#define NT    512

struct Plan {
    unsigned short m1[3][NQ], R1[3][NQ];   // 1q pair masks / sign rows (12-bit)
    unsigned short mE[3][NQ], XE[3][NQ];   // edge pair masks / sign rows
    unsigned short RM[NQ];                 // measurement rows
};

struct CM { float2 m[4]; };

__device__ __forceinline__ float2 cxmul(float2 a, float2 b) {
    return make_float2(a.x*b.x - a.y*b.y, a.x*b.y + a.y*b.x);
}
__device__ __forceinline__ float2 cxadd(float2 a, float2 b) {
    return make_float2(a.x + b.x, a.y + b.y);
}
__device__ __forceinline__ CM mm(const CM& A, const CM& B) {
    CM C;
#pragma unroll
    for (int i = 0; i < 2; i++)
#pragma unroll
        for (int j = 0; j < 2; j++)
            C.m[i*2+j] = cxadd(cxmul(A.m[i*2+0], B.m[0*2+j]),
                               cxmul(A.m[i*2+1], B.m[1*2+j]));
    return C;
}
__device__ __forceinline__ CM RX(float t) {
    float s, c; sincosf(0.5f*t, &s, &c);
    CM M;
    M.m[0] = make_float2(c,0.f);  M.m[1] = make_float2(0.f,-s);
    M.m[2] = make_float2(0.f,-s); M.m[3] = make_float2(c,0.f);
    return M;
}
__device__ __forceinline__ CM RY(float t) {
    float s, c; sincosf(0.5f*t, &s, &c);
    CM M;
    M.m[0] = make_float2(c,0.f); M.m[1] = make_float2(-s,0.f);
    M.m[2] = make_float2(s,0.f); M.m[3] = make_float2(c,0.f);
    return M;
}
__device__ __forceinline__ CM RZ(float t) {
    float s, c; sincosf(0.5f*t, &s, &c);
    CM M;
    M.m[0] = make_float2(c,-s);    M.m[1] = make_float2(0.f,0.f);
    M.m[2] = make_float2(0.f,0.f); M.m[3] = make_float2(c,s);
    return M;
}

__device__ __forceinline__ void apply2(const float2 g[4], float2 &a0, float2 &a1) {
    float2 n0, n1;
    n0.x = g[0].x*a0.x - g[0].y*a0.y + g[1].x*a1.x - g[1].y*a1.y;
    n0.y = g[0].x*a0.y + g[0].y*a0.x + g[1].x*a1.y + g[1].y*a1.x;
    n1.x = g[2].x*a0.x - g[2].y*a0.y + g[3].x*a1.x - g[3].y*a1.y;
    n1.y = g[2].x*a0.y + g[2].y*a0.x + g[3].x*a1.y + g[3].y*a1.x;
    a0 = n0; a1 = n1;
}
__device__ __forceinline__ void applyMix(float c, float ss, float2 &a, float2 &b) {
    float2 na, nb;
    na.x = c*a.x - ss*b.y;  na.y = c*a.y + ss*b.x;
    nb.x = c*b.x - ss*a.y;  nb.y = c*b.y + ss*a.x;
    a = na; b = nb;
}
__device__ __forceinline__ unsigned insert1(unsigned i, int h) {
    return ((i >> h) << (h + 1)) | (i & ((1u << h) - 1u));
}
__device__ __forceinline__ unsigned insert2(unsigned i, int lo, int hi) {
    unsigned p = ((i >> lo) << (lo + 1)) | (i & ((1u << lo) - 1u));
    p = ((p >> hi) << (hi + 1)) | (p & ((1u << hi) - 1u));
    return p;
}
__device__ __forceinline__ int par(unsigned x) { return __popc(x) & 1; }
__device__ __forceinline__ void cfma(float2& acc, float2 a, float2 b) {
    acc.x += a.x*b.x - a.y*b.y;
    acc.y += a.x*b.y + a.y*b.x;
}

// 1q stage over local qubits q0..q10 in 3 sweeps:
//  A: quad(q9,q10) + shuffle(q0..q4)  [masks q0..q4 live in lane bits 0..4]
//  B: quad(q5,q6)   C: quad(q7,q8)
__device__ __forceinline__ void stage1q(const float2 (*gt)[4], const Plan& PL, int blk,
                                        float2* amp, unsigned rank, unsigned t)
{
    {
        const unsigned mA = PL.m1[blk][9],  RA = PL.R1[blk][9];
        const unsigned mB = PL.m1[blk][10], RB = PL.R1[blk][10];
        const int hA = 31 - __clz((int)mA), hB = 31 - __clz((int)mB);
        const int lo = hA < hB ? hA : hB, hi = hA < hB ? hB : hA;
        unsigned p = insert2(t, lo, hi);
        unsigned base = p;
        if (par(p & RA & 0x7FFu) ^ (rank & (RA >> 11))) base ^= mA;
        if (par(p & RB & 0x7FFu) ^ (rank & (RB >> 11))) base ^= mB;
        float2 V[4];
        V[0] = amp[base];      V[1] = amp[base ^ mA];
        V[2] = amp[base ^ mB]; V[3] = amp[base ^ mA ^ mB];
        {
            float2 gA[4], gB[4];
#pragma unroll
            for (int k = 0; k < 4; k++) { gA[k] = gt[9][k]; gB[k] = gt[10][k]; }
            apply2(gA, V[0], V[1]); apply2(gA, V[2], V[3]);
            apply2(gB, V[0], V[2]); apply2(gB, V[1], V[3]);
        }
#pragma unroll
        for (int q = 0; q < 5; q++) {
            const unsigned mc = PL.m1[blk][q], R = PL.R1[blk][q];
            const int bit = par(base & R & 0x7FFu) ^ (rank & (R >> 11));
            const float2 gd = bit ? gt[q][3] : gt[q][0];
            const float2 go = bit ? gt[q][2] : gt[q][1];
#pragma unroll
            for (int r = 0; r < 4; r++) {
                float px = __shfl_xor_sync(0xffffffffu, V[r].x, mc);
                float py = __shfl_xor_sync(0xffffffffu, V[r].y, mc);
                float2 nv;
                nv.x = gd.x*V[r].x - gd.y*V[r].y + go.x*px - go.y*py;
                nv.y = gd.x*V[r].y + gd.y*V[r].x + go.x*py + go.y*px;
                V[r] = nv;
            }
        }
        amp[base] = V[0];      amp[base ^ mA] = V[1];
        amp[base ^ mB] = V[2]; amp[base ^ mA ^ mB] = V[3];
    }
    __syncthreads();
#pragma unroll
    for (int sw = 0; sw < 2; sw++) {
        const int qA = 5 + 2*sw, qB = 6 + 2*sw;
        const unsigned mA = PL.m1[blk][qA], RA = PL.R1[blk][qA];
        const unsigned mB = PL.m1[blk][qB], RB = PL.R1[blk][qB];
        const int hA = 31 - __clz((int)mA), hB = 31 - __clz((int)mB);
        const int lo = hA < hB ? hA : hB, hi = hA < hB ? hB : hA;
        float2 gA[4], gB[4];
#pragma unroll
        for (int k = 0; k < 4; k++) { gA[k] = gt[qA][k]; gB[k] = gt[qB][k]; }
        unsigned p = insert2(t, lo, hi);
        unsigned base = p;
        if (par(p & RA & 0x7FFu) ^ (rank & (RA >> 11))) base ^= mA;
        if (par(p & RB & 0x7FFu) ^ (rank & (RB >> 11))) base ^= mB;
        const unsigned i10 = base ^ mA, i01 = base ^ mB, i11 = base ^ mA ^ mB;
        float2 a00 = amp[base], a10 = amp[i10], a01 = amp[i01], a11 = amp[i11];
        apply2(gA, a00, a10); apply2(gA, a01, a11);
        apply2(gB, a00, a01); apply2(gB, a10, a11);
        amp[base] = a00; amp[i10] = a10; amp[i01] = a01; amp[i11] = a11;
        __syncthreads();
    }
}

__global__ void __launch_bounds__(NT, 1) __cluster_dims__(2, 1, 1)
qsim_kernel(const float* __restrict__ data,
            const float* __restrict__ es,
            const float* __restrict__ eb,
            const float* __restrict__ eta,
            const float* __restrict__ ew_zz,
            const float* __restrict__ ew_xx,
            const float* __restrict__ ew_yy,
            const float* __restrict__ nb_z,
            const float* __restrict__ nb_x,
            const float* __restrict__ nb_y,
            const float* __restrict__ rots,
            Plan PL,
            float* __restrict__ out)
{
    __shared__ float2 amp[HDIM];
    __shared__ float2 gT1[NQ][4];
    __shared__ float2 gT2[NQ][4];
    __shared__ float2 gX[2][4];        // deferred bias q11 gate, by block parity
    __shared__ float  sC[NQ], sS[NQ], sH[NQ];
    __shared__ float  red[NT/32][NQ];
    __shared__ float  sums[NQ];

    cg::cluster_group cl = cg::this_cluster();
    const unsigned rank = blockIdx.x & 1u;
    const int b = blockIdx.x >> 1;
    const unsigned t = threadIdx.x;
    float2* peer = cl.map_shared_rank(amp, rank ^ 1u);
    float*  psums = cl.map_shared_rank(sums, 1u);

    for (int blk = 0; blk < 3; blk++) {
        // ---- per-block gate tables (threads 0..11) ----
        if (t < NQ) {
            const int q = t;
            float d  = data[b*NQ + q];
            float ax = es[q*3+0]*d + eb[q*3+0];
            float ay = es[q*3+1]*d + eb[q*3+1];
            float az = es[q*3+2]*d + eb[q*3+2];
            CM M;
            if (blk == 0)      M = mm(RZ(az), mm(RY(ay), RX(ax)));
            else if (blk == 1) M = mm(RY(ay), RX(ax));
            else               M = mm(RZ(az), RY(ay));
#pragma unroll
            for (int k = 0; k < 4; k++) gT1[q][k] = M.m[k];

            float bias = (blk == 0) ? nb_z[q] : (blk == 1) ? nb_x[q] : nb_y[q];
            CM Mb = (blk == 0) ? RZ(bias) : (blk == 1) ? RX(bias) : RY(bias);
            const float* rr = rots + blk*(NQ*3) + q*3;
            CM M2 = mm(RZ(rr[2]), mm(RY(rr[1]), mm(RX(rr[0]), Mb)));
#pragma unroll
            for (int k = 0; k < 4; k++) gT2[q][k] = M2.m[k];
            if (q == 11) {
#pragma unroll
                for (int k = 0; k < 4; k++) gX[blk & 1][k] = M2.m[k];
            }

            float ew = (blk == 0) ? ew_zz[q] : (blk == 1) ? ew_xx[q] : ew_yy[q];
            float h = 0.5f * eta[blk] * ew;
            float s, c; sincosf(h, &s, &c);
            sC[q] = c; sS[q] = s; sH[q] = h;
        }
        __syncthreads();

        if (blk == 0) {
            // ---- product-state init (encoding on |0..0>) + fused ZZ phase ----
            float2 prod = rank ? gT1[11][2] : gT1[11][0];
#pragma unroll
            for (int q = 0; q < 9; q++) {
                float2 f = ((t >> q) & 1) ? gT1[q][2] : gT1[q][0];
                prod = cxmul(prod, f);
            }
#pragma unroll
            for (int j = 0; j < 4; j++) {
                unsigned l = t + j*NT;
                float2 v = cxmul(prod, (j & 1) ? gT1[9][2]  : gT1[9][0]);
                v = cxmul(v,           (j & 2) ? gT1[10][2] : gT1[10][0]);
                unsigned k12 = l | (rank << 11);
                float phi = 0.0f;
#pragma unroll
                for (int e = 0; e < NQ; e++)
                    phi += par(k12 & PL.XE[0][e]) ? sH[e] : -sH[e];
                float sp, cp; __sincosf(phi, &sp, &cp);
                amp[l] = make_float2(v.x*cp - v.y*sp, v.x*sp + v.y*cp);
            }
            __syncthreads();
        } else {
            // ---- fused cross exchange: bias(blk-1)@q11 then enc(blk)@q11 ----
            const unsigned ma = PL.m1[blk-1][11], mb = PL.m1[blk][11];
            float2 ga[4], gb[4];
#pragma unroll
            for (int k = 0; k < 4; k++) { ga[k] = gX[(blk-1) & 1][k]; gb[k] = gT1[11][k]; }
            const float2 ga_d  = rank ? ga[3] : ga[0];
            const float2 ga_o  = rank ? ga[2] : ga[1];
            const float2 ga_d2 = rank ? ga[0] : ga[3];
            const float2 ga_o2 = rank ? ga[1] : ga[2];
            const float2 gb_d  = rank ? gb[3] : gb[0];
            const float2 gb_o  = rank ? gb[2] : gb[1];
            const float2 C1 = cxmul(gb_d, ga_d);
            const float2 C2 = cxmul(gb_d, ga_o);
            const float2 C3 = cxmul(gb_o, ga_d2);
            const float2 C4 = cxmul(gb_o, ga_o2);
            const unsigned m12 = (ma ^ mb) & 0x7FFu;
            const int h12 = 31 - __clz((int)m12);
            const unsigned pa = ma & 0x7FFu, pb = mb & 0x7FFu;
            cl.sync();
            float2 r0[2], r1[2], q0[2], q1[2];
#pragma unroll
            for (int j = 0; j < 2; j++) {
                unsigned base = insert1(t + j*NT, h12);
                r0[j] = amp[base];       r1[j] = amp[base ^ m12];
                q0[j] = peer[base ^ pa]; q1[j] = peer[base ^ pb];
            }
            cl.sync();
#pragma unroll
            for (int j = 0; j < 2; j++) {
                unsigned base = insert1(t + j*NT, h12);
                float2 o0 = make_float2(0.f, 0.f), o1 = make_float2(0.f, 0.f);
                cfma(o0, C1, r0[j]); cfma(o0, C2, q0[j]);
                cfma(o0, C3, q1[j]); cfma(o0, C4, r1[j]);
                cfma(o1, C1, r1[j]); cfma(o1, C2, q1[j]);
                cfma(o1, C3, q0[j]); cfma(o1, C4, r0[j]);
                amp[base] = o0; amp[base ^ m12] = o1;
            }
            __syncthreads();

            // ---- encoding locals q0..q10: 3 sweeps ----
            stage1q(gT1, PL, blk, amp, rank, t);

            // ---- Ising edges: 3 local sweeps + shuffled tail + cross pair ----
#pragma unroll
            for (int sw = 0; sw < 3; sw++) {
                const int e1 = 1 + 2*sw, e2 = 2 + 2*sw;
                const unsigned m1 = PL.mE[blk][e1], m2 = PL.mE[blk][e2];
                const float c1 = sC[e1], s1 = sS[e1];
                const float c2 = sC[e2], s2 = sS[e2];
                const int h1 = 31 - __clz((int)m1), h2 = 31 - __clz((int)m2);
                const int lo = h1 < h2 ? h1 : h2, hi = h1 < h2 ? h2 : h1;
                unsigned p = insert2(t, lo, hi);
                const unsigned iA = p ^ m1, iB = p ^ m2, iC = p ^ m1 ^ m2;
                float2 V[4];
                V[0] = amp[p]; V[1] = amp[iA]; V[2] = amp[iB]; V[3] = amp[iC];
                if (blk == 1) {
                    applyMix(c1, -s1, V[0], V[1]); applyMix(c1, -s1, V[2], V[3]);
                    applyMix(c2, -s2, V[0], V[2]); applyMix(c2, -s2, V[1], V[3]);
                } else {
                    const unsigned X1 = PL.XE[2][e1], X2 = PL.XE[2][e2];
                    const unsigned adj1 = par(m2 & X1 & 0x7FFu);
                    const unsigned adj2 = par(m1 & X2 & 0x7FFu);
                    unsigned t1 = par(p & X1 & 0x7FFu) ^ (rank & (X1 >> 11));
                    applyMix(c1, t1 ? -s1 : s1, V[0], V[1]);
                    applyMix(c1, (t1 ^ adj1) ? -s1 : s1, V[2], V[3]);
                    unsigned t2 = par(p & X2 & 0x7FFu) ^ (rank & (X2 >> 11));
                    applyMix(c2, t2 ? -s2 : s2, V[0], V[2]);
                    applyMix(c2, (t2 ^ adj2) ? -s2 : s2, V[1], V[3]);
                }
                if (sw == 0) {
                    // shuffle edges e7..e10 (masks in lane bits 0..4)
#pragma unroll
                    for (int c = 7; c <= 10; c++) {
                        const unsigned mc = PL.mE[blk][c];
                        const float cc = sC[c], sv = sS[c];
                        float ss;
                        if (blk == 1) ss = -sv;
                        else {
                            const unsigned X = PL.XE[2][c];
                            const int bt = 31 - __clz((int)mc);
                            int sg = par(p & X & 0x7FFu) ^ (rank & (X >> 11));
                            sg ^= ((p >> bt) & 1) & par(mc & X & 0x7FFu);
                            ss = sg ? -sv : sv;
                        }
#pragma unroll
                        for (int r = 0; r < 4; r++) {
                            float px = __shfl_xor_sync(0xffffffffu, V[r].x, mc);
                            float py = __shfl_xor_sync(0xffffffffu, V[r].y, mc);
                            float2 nv;
                            nv.x = cc*V[r].x - ss*py;
                            nv.y = cc*V[r].y + ss*px;
                            V[r] = nv;
                        }
                    }
                }
                amp[p] = V[0]; amp[iA] = V[1]; amp[iB] = V[2]; amp[iC] = V[3];
                __syncthreads();
            }
            {
                // cross pair (e11, e0), pair-based
                const int e1 = 11, e2 = 0;
                const unsigned m1e = PL.mE[blk][e1], m2e = PL.mE[blk][e2];
                const float c1 = sC[e1], s1 = sS[e1];
                const float c2 = sC[e2], s2 = sS[e2];
                const float cc = c1 * c2;
                const unsigned X1 = PL.XE[2][e1], X2 = PL.XE[2][e2];
                const int f1 = (blk == 2) ? par(m2e & X1 & 0xFFFu) : 0;
                const unsigned m12 = (m1e ^ m2e) & 0x7FFu;
                const int h12 = 31 - __clz((int)m12);
                const unsigned p1m = m1e & 0x7FFu, p2m = m2e & 0x7FFu;
                cl.sync();
                float2 A0[2], A1[2], P1[2], P2[2];
#pragma unroll
                for (int j = 0; j < 2; j++) {
                    unsigned base = insert1(t + j*NT, h12);
                    A0[j] = amp[base];        A1[j] = amp[base ^ m12];
                    P1[j] = peer[base ^ p1m]; P2[j] = peer[base ^ p2m];
                }
                cl.sync();
#pragma unroll
                for (int j = 0; j < 2; j++) {
                    unsigned base = insert1(t + j*NT, h12);
                    float w1, w2, w1b, w2b;
                    if (blk == 1) { w1 = -s1; w2 = -s2; w1b = w1; w2b = w2; }
                    else {
                        unsigned k12  = base | (rank << 11);
                        unsigned k12b = k12 ^ m12;
                        w1  = par(k12  & X1) ? -s1 : s1;
                        w2  = par(k12  & X2) ? -s2 : s2;
                        w1b = par(k12b & X1) ? -s1 : s1;
                        w2b = par(k12b & X2) ? -s2 : s2;
                    }
                    {
                        float w1p = f1 ? -w1 : w1;
                        float T4 = -(w2 * w1p);
                        float k1 = c2 * w1, k2 = c1 * w2;
                        float2 r;
                        r.x = cc*A0[j].x - k1*P1[j].y - k2*P2[j].y + T4*A1[j].x;
                        r.y = cc*A0[j].y + k1*P1[j].x + k2*P2[j].x + T4*A1[j].y;
                        amp[base] = r;
                    }
                    {
                        float w1p = f1 ? -w1b : w1b;
                        float T4 = -(w2b * w1p);
                        float k1 = c2 * w1b, k2 = c1 * w2b;
                        float2 r;
                        r.x = cc*A1[j].x - k1*P2[j].y - k2*P1[j].y + T4*A0[j].x;
                        r.y = cc*A1[j].y + k1*P2[j].x + k2*P1[j].x + T4*A0[j].y;
                        amp[base ^ m12] = r;
                    }
                }
                __syncthreads();
            }
        }

        // ---- bias + trainable rots locals q0..q10 (q11 deferred) ----
        stage1q(gT2, PL, blk, amp, rank, t);
    }

    // ---- final deferred bias(blk2)@q11 cross ----
    {
        const unsigned ma = PL.m1[2][11];
        float2 g[4];
#pragma unroll
        for (int k = 0; k < 4; k++) g[k] = gT2[11][k];
        const float2 gd = rank ? g[3] : g[0];
        const float2 go = rank ? g[2] : g[1];
        const unsigned pm = ma & 0x7FFu;
        cl.sync();
        float2 pv[4];
#pragma unroll
        for (int j = 0; j < 4; j++)
            pv[j] = peer[(t + j*NT) ^ pm];
        cl.sync();
#pragma unroll
        for (int j = 0; j < 4; j++) {
            unsigned l = t + j*NT;
            float2 a = amp[l];
            float2 r;
            r.x = gd.x*a.x - gd.y*a.y + go.x*pv[j].x - go.y*pv[j].y;
            r.y = gd.x*a.y + gd.y*a.x + go.x*pv[j].y + go.y*pv[j].x;
            amp[l] = r;
        }
    }

    // ---- measurement over local half ----
    float acc[NQ];
#pragma unroll
    for (int i = 0; i < NQ; i++) acc[i] = 0.0f;
#pragma unroll
    for (int j = 0; j < 4; j++) {
        unsigned l = t + j*NT;
        float2 a = amp[l];
        float pr = a.x*a.x + a.y*a.y;
#pragma unroll
        for (int i = 0; i < NQ; i++) {
            unsigned Rm = PL.RM[i];
            int sg = par(l & Rm & 0x7FFu) ^ (rank & (Rm >> 11));
            acc[i] += sg ? -pr : pr;
        }
    }
#pragma unroll
    for (int off = 16; off > 0; off >>= 1)
#pragma unroll
        for (int i = 0; i < NQ; i++)
            acc[i] += __shfl_down_sync(0xffffffffu, acc[i], off);
    const int wid = t >> 5;
    if ((t & 31) == 0) {
#pragma unroll
        for (int i = 0; i < NQ; i++) red[wid][i] = acc[i];
    }
    __syncthreads();
    if (t < NQ) {
        float s = 0.0f;
#pragma unroll
        for (int w = 0; w < NT/32; w++) s += red[w][t];
        sums[t] = s;
    }
    __syncthreads();
    cl.sync();
    if (rank == 0 && t < NQ)
        out[b*NQ + t] = sums[t] + psums[t];
    cl.sync();
}

// ---- host: GF(2) algebra of the CNOT ring ----
static inline unsigned Gm(unsigned j) {
    unsigned r = (j ^ (j >> 1)) & 0xFFFu;
    r ^= (j >> 11) & 1u;
    return r;
}
static inline unsigned Fm(unsigned k) {
    unsigned p = k;
    p ^= p >> 1; p ^= p >> 2; p ^= p >> 4; p ^= p >> 8;
    p &= 0xFFFu;
    return (p & 0xFFEu) | ((p ^ (k >> 11)) & 1u);
}

extern "C" void kernel_launch(void* const* d_in, const int* in_sizes, int n_in,
                              void* d_out, int out_size) {
    const float* data   = (const float*)d_in[0];
    const float* es     = (const float*)d_in[1];
    const float* eb     = (const float*)d_in[2];
    const float* eta    = (const float*)d_in[3];
    const float* ew_zz  = (const float*)d_in[4];
    const float* ew_xx  = (const float*)d_in[5];
    const float* ew_yy  = (const float*)d_in[6];
    const float* nb_z   = (const float*)d_in[7];
    const float* nb_x   = (const float*)d_in[8];
    const float* nb_y   = (const float*)d_in[9];
    const float* rots   = (const float*)d_in[10];
    float* out = (float*)d_out;

    Plan PL;
    unsigned rows[4][12];
    for (int p = 0; p < 4; p++) {
        unsigned col[12];
        for (int j = 0; j < 12; j++) {
            unsigned v = 1u << j;
            for (int it = 0; it < p; it++) v = Fm(v);
            col[j] = v;
        }
        for (int q = 0; q < 12; q++) {
            unsigned r = 0;
            for (int j = 0; j < 12; j++) r |= ((col[j] >> q) & 1u) << j;
            rows[p][q] = r;
        }
    }
    for (int blk = 0; blk < 3; blk++) {
        for (int q = 0; q < 12; q++) {
            unsigned m = 1u << q;
            for (int it = 0; it < blk; it++) m = Gm(m);
            PL.m1[blk][q] = (unsigned short)m;
            PL.R1[blk][q] = (unsigned short)rows[blk][q];
        }
        for (int e = 0; e < 12; e++) {
            unsigned a  = (e < 11) ? (unsigned)(11 - e) : 11u;
            unsigned b2 = (e < 11) ? (unsigned)(10 - e) : 0u;
            unsigned M = (1u << a) | (1u << b2);
            unsigned m = M;
            for (int it = 0; it < blk; it++) m = Gm(m);
            PL.mE[blk][e] = (unsigned short)m;
            PL.XE[blk][e] = (unsigned short)(rows[blk][a] ^ rows[blk][b2]);
        }
    }
    for (int i = 0; i < 12; i++) PL.RM[i] = (unsigned short)rows[3][11 - i];

    int B = in_sizes[0] / NQ;   // 64
    qsim_kernel<<<B * 2, NT>>>(data, es, eb, eta, ew_zz, ew_xx, ew_yy,
                               nb_z, nb_x, nb_y, rots, PL, out);
}

// round 6
// speedup vs baseline: 2.7130x; 1.3355x over previous
#include <cuda_runtime.h>
#include <cooperative_groups.h>
namespace cg = cooperative_groups;

#define NQ    12
#define HDIM  2048      // per-CTA half state
#define NT    512

struct Plan {
    unsigned short m1[3][NQ], R1[3][NQ];   // 1q pair masks / sign rows (12-bit)
    unsigned short mE[3][NQ], XE[3][NQ];   // edge pair masks / sign rows
    unsigned short RM[NQ];                 // measurement rows
};

struct CM { float2 m[4]; };

__device__ __forceinline__ float2 cxmul(float2 a, float2 b) {
    return make_float2(a.x*b.x - a.y*b.y, a.x*b.y + a.y*b.x);
}
__device__ __forceinline__ float2 cxadd(float2 a, float2 b) {
    return make_float2(a.x + b.x, a.y + b.y);
}
__device__ __forceinline__ CM mm(const CM& A, const CM& B) {
    CM C;
#pragma unroll
    for (int i = 0; i < 2; i++)
#pragma unroll
        for (int j = 0; j < 2; j++)
            C.m[i*2+j] = cxadd(cxmul(A.m[i*2+0], B.m[0*2+j]),
                               cxmul(A.m[i*2+1], B.m[1*2+j]));
    return C;
}
__device__ __forceinline__ CM RX(float t) {
    float s, c; sincosf(0.5f*t, &s, &c);
    CM M;
    M.m[0] = make_float2(c,0.f);  M.m[1] = make_float2(0.f,-s);
    M.m[2] = make_float2(0.f,-s); M.m[3] = make_float2(c,0.f);
    return M;
}
__device__ __forceinline__ CM RY(float t) {
    float s, c; sincosf(0.5f*t, &s, &c);
    CM M;
    M.m[0] = make_float2(c,0.f); M.m[1] = make_float2(-s,0.f);
    M.m[2] = make_float2(s,0.f); M.m[3] = make_float2(c,0.f);
    return M;
}
__device__ __forceinline__ CM RZ(float t) {
    float s, c; sincosf(0.5f*t, &s, &c);
    CM M;
    M.m[0] = make_float2(c,-s);    M.m[1] = make_float2(0.f,0.f);
    M.m[2] = make_float2(0.f,0.f); M.m[3] = make_float2(c,s);
    return M;
}

__device__ __forceinline__ void apply2(const float2 g[4], float2 &a0, float2 &a1) {
    float2 n0, n1;
    n0.x = g[0].x*a0.x - g[0].y*a0.y + g[1].x*a1.x - g[1].y*a1.y;
    n0.y = g[0].x*a0.y + g[0].y*a0.x + g[1].x*a1.y + g[1].y*a1.x;
    n1.x = g[2].x*a0.x - g[2].y*a0.y + g[3].x*a1.x - g[3].y*a1.y;
    n1.y = g[2].x*a0.y + g[2].y*a0.x + g[3].x*a1.y + g[3].y*a1.x;
    a0 = n0; a1 = n1;
}
__device__ __forceinline__ void applyMix(float c, float ss, float2 &a, float2 &b) {
    float2 na, nb;
    na.x = c*a.x - ss*b.y;  na.y = c*a.y + ss*b.x;
    nb.x = c*b.x - ss*a.y;  nb.y = c*b.y + ss*a.x;
    a = na; b = nb;
}
__device__ __forceinline__ unsigned insert1(unsigned i, int h) {
    return ((i >> h) << (h + 1)) | (i & ((1u << h) - 1u));
}
__device__ __forceinline__ unsigned insert2(unsigned i, int lo, int hi) {
    unsigned p = ((i >> lo) << (lo + 1)) | (i & ((1u << lo) - 1u));
    p = ((p >> hi) << (hi + 1)) | (p & ((1u << hi) - 1u));
    return p;
}
__device__ __forceinline__ int par(unsigned x) { return __popc(x) & 1; }
__device__ __forceinline__ void cfma(float2& acc, float2 a, float2 b) {
    acc.x += a.x*b.x - a.y*b.y;
    acc.y += a.x*b.y + a.y*b.x;
}

// 1q stage over local qubits q0..q10 in 3 sweeps:
//  A: quad(q9,q10) + shuffle(q0..q4)   B: quad(q5,q6)   C: quad(q7,q8)
__device__ __forceinline__ void stage1q(const float2 (*gt)[4], const Plan& PL, int blk,
                                        float2* amp, unsigned rank, unsigned t)
{
    {
        const unsigned mA = PL.m1[blk][9],  RA = PL.R1[blk][9];
        const unsigned mB = PL.m1[blk][10], RB = PL.R1[blk][10];
        const int hA = 31 - __clz((int)mA), hB = 31 - __clz((int)mB);
        const int lo = hA < hB ? hA : hB, hi = hA < hB ? hB : hA;
        unsigned p = insert2(t, lo, hi);
        unsigned base = p;
        if (par(p & RA & 0x7FFu) ^ (rank & (RA >> 11))) base ^= mA;
        if (par(p & RB & 0x7FFu) ^ (rank & (RB >> 11))) base ^= mB;
        float2 V[4];
        V[0] = amp[base];      V[1] = amp[base ^ mA];
        V[2] = amp[base ^ mB]; V[3] = amp[base ^ mA ^ mB];
        {
            float2 gA[4], gB[4];
#pragma unroll
            for (int k = 0; k < 4; k++) { gA[k] = gt[9][k]; gB[k] = gt[10][k]; }
            apply2(gA, V[0], V[1]); apply2(gA, V[2], V[3]);
            apply2(gB, V[0], V[2]); apply2(gB, V[1], V[3]);
        }
#pragma unroll
        for (int q = 0; q < 5; q++) {
            const unsigned mc = PL.m1[blk][q], R = PL.R1[blk][q];
            const int bit = par(base & R & 0x7FFu) ^ (rank & (R >> 11));
            const float2 gd = bit ? gt[q][3] : gt[q][0];
            const float2 go = bit ? gt[q][2] : gt[q][1];
#pragma unroll
            for (int r = 0; r < 4; r++) {
                float px = __shfl_xor_sync(0xffffffffu, V[r].x, mc);
                float py = __shfl_xor_sync(0xffffffffu, V[r].y, mc);
                float2 nv;
                nv.x = gd.x*V[r].x - gd.y*V[r].y + go.x*px - go.y*py;
                nv.y = gd.x*V[r].y + gd.y*V[r].x + go.x*py + go.y*px;
                V[r] = nv;
            }
        }
        amp[base] = V[0];      amp[base ^ mA] = V[1];
        amp[base ^ mB] = V[2]; amp[base ^ mA ^ mB] = V[3];
    }
    __syncthreads();
#pragma unroll
    for (int sw = 0; sw < 2; sw++) {
        const int qA = 5 + 2*sw, qB = 6 + 2*sw;
        const unsigned mA = PL.m1[blk][qA], RA = PL.R1[blk][qA];
        const unsigned mB = PL.m1[blk][qB], RB = PL.R1[blk][qB];
        const int hA = 31 - __clz((int)mA), hB = 31 - __clz((int)mB);
        const int lo = hA < hB ? hA : hB, hi = hA < hB ? hB : hA;
        float2 gA[4], gB[4];
#pragma unroll
        for (int k = 0; k < 4; k++) { gA[k] = gt[qA][k]; gB[k] = gt[qB][k]; }
        unsigned p = insert2(t, lo, hi);
        unsigned base = p;
        if (par(p & RA & 0x7FFu) ^ (rank & (RA >> 11))) base ^= mA;
        if (par(p & RB & 0x7FFu) ^ (rank & (RB >> 11))) base ^= mB;
        const unsigned i10 = base ^ mA, i01 = base ^ mB, i11 = base ^ mA ^ mB;
        float2 a00 = amp[base], a10 = amp[i10], a01 = amp[i01], a11 = amp[i11];
        apply2(gA, a00, a10); apply2(gA, a01, a11);
        apply2(gB, a00, a01); apply2(gB, a10, a11);
        amp[base] = a00; amp[i10] = a10; amp[i01] = a01; amp[i11] = a11;
        __syncthreads();
    }
}

__global__ void __launch_bounds__(NT, 1) __cluster_dims__(2, 1, 1)
qsim_kernel(const float* __restrict__ data,
            const float* __restrict__ es,
            const float* __restrict__ eb,
            const float* __restrict__ eta,
            const float* __restrict__ ew_zz,
            const float* __restrict__ ew_xx,
            const float* __restrict__ ew_yy,
            const float* __restrict__ nb_z,
            const float* __restrict__ nb_x,
            const float* __restrict__ nb_y,
            const float* __restrict__ rots,
            Plan PL,
            float* __restrict__ out)
{
    __shared__ float2 ampA[HDIM];
    __shared__ float2 ampB[HDIM];
    __shared__ float2 gT1[3][NQ][4];
    __shared__ float2 gT2[3][NQ][4];
    __shared__ float  sC[3][NQ], sS[3][NQ], sH0[NQ];
    __shared__ float  red[NT/32][NQ];
    __shared__ float  sums[NQ];

    cg::cluster_group cl = cg::this_cluster();
    const unsigned rank = blockIdx.x & 1u;
    const int b = blockIdx.x >> 1;
    const unsigned t = threadIdx.x;
    float2* peerA = cl.map_shared_rank(ampA, rank ^ 1u);
    float2* peerB = cl.map_shared_rank(ampB, rank ^ 1u);
    float*  psums = cl.map_shared_rank(sums, 1u);

    // ---- ALL gate tables upfront, 36 threads in parallel ----
    if (t < 36) {
        const int blk = t / 12, q = t % 12;
        float d  = data[b*NQ + q];
        float ax = es[q*3+0]*d + eb[q*3+0];
        float ay = es[q*3+1]*d + eb[q*3+1];
        float az = es[q*3+2]*d + eb[q*3+2];
        CM M;
        if (blk == 0)      M = mm(RZ(az), mm(RY(ay), RX(ax)));
        else if (blk == 1) M = mm(RY(ay), RX(ax));
        else               M = mm(RZ(az), RY(ay));
#pragma unroll
        for (int k = 0; k < 4; k++) gT1[blk][q][k] = M.m[k];

        float bias = (blk == 0) ? nb_z[q] : (blk == 1) ? nb_x[q] : nb_y[q];
        CM Mb = (blk == 0) ? RZ(bias) : (blk == 1) ? RX(bias) : RY(bias);
        const float* rr = rots + blk*(NQ*3) + q*3;
        CM M2 = mm(RZ(rr[2]), mm(RY(rr[1]), mm(RX(rr[0]), Mb)));
#pragma unroll
        for (int k = 0; k < 4; k++) gT2[blk][q][k] = M2.m[k];

        float ew = (blk == 0) ? ew_zz[q] : (blk == 1) ? ew_xx[q] : ew_yy[q];
        float h = 0.5f * eta[blk] * ew;
        float s, c; sincosf(h, &s, &c);
        sC[blk][q] = c; sS[blk][q] = s;
        if (blk == 0) sH0[q] = h;
    }
    __syncthreads();

    float2* cur  = ampA;
    float2* nxt  = ampB;
    float2* pcur = peerA;
    float2* pnxt = peerB;

    // ---- blk0: product-state init (encoding on |0..0>) + fused ZZ phase ----
    {
        float2 prod = rank ? gT1[0][11][2] : gT1[0][11][0];
#pragma unroll
        for (int q = 0; q < 9; q++) {
            float2 f = ((t >> q) & 1) ? gT1[0][q][2] : gT1[0][q][0];
            prod = cxmul(prod, f);
        }
#pragma unroll
        for (int j = 0; j < 4; j++) {
            unsigned l = t + j*NT;
            float2 v = cxmul(prod, (j & 1) ? gT1[0][9][2]  : gT1[0][9][0]);
            v = cxmul(v,           (j & 2) ? gT1[0][10][2] : gT1[0][10][0]);
            unsigned k12 = l | (rank << 11);
            float phi = 0.0f;
#pragma unroll
            for (int e = 0; e < NQ; e++)
                phi += par(k12 & PL.XE[0][e]) ? sH0[e] : -sH0[e];
            float sp, cp; __sincosf(phi, &sp, &cp);
            cur[l] = make_float2(v.x*cp - v.y*sp, v.x*sp + v.y*cp);
        }
        __syncthreads();
    }
    // blk0 bias+rots locals (q11 deferred)
    stage1q(gT2[0], PL, 0, cur, rank, t);

    for (int blk = 1; blk < 3; blk++) {
        // ---- fused cross exchange: bias(blk-1)@q11 then enc(blk)@q11 ----
        {
            const unsigned ma = PL.m1[blk-1][11], mb = PL.m1[blk][11];
            const float2* ga = gT2[blk-1][11];
            const float2* gb = gT1[blk][11];
            const float2 ga_d  = rank ? ga[3] : ga[0];
            const float2 ga_o  = rank ? ga[2] : ga[1];
            const float2 ga_d2 = rank ? ga[0] : ga[3];
            const float2 ga_o2 = rank ? ga[1] : ga[2];
            const float2 gb_d  = rank ? gb[3] : gb[0];
            const float2 gb_o  = rank ? gb[2] : gb[1];
            const float2 C1 = cxmul(gb_d, ga_d);
            const float2 C2 = cxmul(gb_d, ga_o);
            const float2 C3 = cxmul(gb_o, ga_d2);
            const float2 C4 = cxmul(gb_o, ga_o2);
            const unsigned m12 = (ma ^ mb) & 0x7FFu;
            const int h12 = 31 - __clz((int)m12);
            const unsigned pa = ma & 0x7FFu, pb = mb & 0x7FFu;
            cl.sync();
#pragma unroll
            for (int j = 0; j < 2; j++) {
                unsigned base = insert1(t + j*NT, h12);
                float2 r0 = cur[base],       r1 = cur[base ^ m12];
                float2 q0 = pcur[base ^ pa], q1 = pcur[base ^ pb];
                float2 o0 = make_float2(0.f, 0.f), o1 = make_float2(0.f, 0.f);
                cfma(o0, C1, r0); cfma(o0, C2, q0);
                cfma(o0, C3, q1); cfma(o0, C4, r1);
                cfma(o1, C1, r1); cfma(o1, C2, q1);
                cfma(o1, C3, q0); cfma(o1, C4, r0);
                nxt[base] = o0; nxt[base ^ m12] = o1;
            }
            { float2* s = cur; cur = nxt; nxt = s; }
            { float2* s = pcur; pcur = pnxt; pnxt = s; }
            __syncthreads();
        }

        // ---- encoding locals q0..q10: 3 sweeps ----
        stage1q(gT1[blk], PL, blk, cur, rank, t);

        // ---- Ising edges: 3 local sweeps (first carries shuffled e7..e10) ----
#pragma unroll
        for (int sw = 0; sw < 3; sw++) {
            const int e1 = 1 + 2*sw, e2 = 2 + 2*sw;
            const unsigned m1 = PL.mE[blk][e1], m2 = PL.mE[blk][e2];
            const float c1 = sC[blk][e1], s1 = sS[blk][e1];
            const float c2 = sC[blk][e2], s2 = sS[blk][e2];
            const int h1 = 31 - __clz((int)m1), h2 = 31 - __clz((int)m2);
            const int lo = h1 < h2 ? h1 : h2, hi = h1 < h2 ? h2 : h1;
            unsigned p = insert2(t, lo, hi);
            const unsigned iA = p ^ m1, iB = p ^ m2, iC = p ^ m1 ^ m2;
            float2 V[4];
            V[0] = cur[p]; V[1] = cur[iA]; V[2] = cur[iB]; V[3] = cur[iC];
            if (blk == 1) {
                applyMix(c1, -s1, V[0], V[1]); applyMix(c1, -s1, V[2], V[3]);
                applyMix(c2, -s2, V[0], V[2]); applyMix(c2, -s2, V[1], V[3]);
            } else {
                const unsigned X1 = PL.XE[2][e1], X2 = PL.XE[2][e2];
                const unsigned adj1 = par(m2 & X1 & 0x7FFu);
                const unsigned adj2 = par(m1 & X2 & 0x7FFu);
                unsigned t1 = par(p & X1 & 0x7FFu) ^ (rank & (X1 >> 11));
                applyMix(c1, t1 ? -s1 : s1, V[0], V[1]);
                applyMix(c1, (t1 ^ adj1) ? -s1 : s1, V[2], V[3]);
                unsigned t2 = par(p & X2 & 0x7FFu) ^ (rank & (X2 >> 11));
                applyMix(c2, t2 ? -s2 : s2, V[0], V[2]);
                applyMix(c2, (t2 ^ adj2) ? -s2 : s2, V[1], V[3]);
            }
            if (sw == 0) {
#pragma unroll
                for (int c = 7; c <= 10; c++) {
                    const unsigned mc = PL.mE[blk][c];
                    const float cc = sC[blk][c], sv = sS[blk][c];
                    float ss;
                    if (blk == 1) ss = -sv;
                    else {
                        const unsigned X = PL.XE[2][c];
                        const int bt = 31 - __clz((int)mc);
                        int sg = par(p & X & 0x7FFu) ^ (rank & (X >> 11));
                        sg ^= ((p >> bt) & 1) & par(mc & X & 0x7FFu);
                        ss = sg ? -sv : sv;
                    }
#pragma unroll
                    for (int r = 0; r < 4; r++) {
                        float px = __shfl_xor_sync(0xffffffffu, V[r].x, mc);
                        float py = __shfl_xor_sync(0xffffffffu, V[r].y, mc);
                        float2 nv;
                        nv.x = cc*V[r].x - ss*py;
                        nv.y = cc*V[r].y + ss*px;
                        V[r] = nv;
                    }
                }
            }
            cur[p] = V[0]; cur[iA] = V[1]; cur[iB] = V[2]; cur[iC] = V[3];
            __syncthreads();
        }

        // ---- cross pair (e11, e0), pair-based ----
        {
            const int e1 = 11, e2 = 0;
            const unsigned m1e = PL.mE[blk][e1], m2e = PL.mE[blk][e2];
            const float c1 = sC[blk][e1], s1 = sS[blk][e1];
            const float c2 = sC[blk][e2], s2 = sS[blk][e2];
            const float cc = c1 * c2;
            const unsigned X1 = PL.XE[2][e1], X2 = PL.XE[2][e2];
            const int f1 = (blk == 2) ? par(m2e & X1 & 0xFFFu) : 0;
            const unsigned m12 = (m1e ^ m2e) & 0x7FFu;
            const int h12 = 31 - __clz((int)m12);
            const unsigned p1m = m1e & 0x7FFu, p2m = m2e & 0x7FFu;
            cl.sync();
#pragma unroll
            for (int j = 0; j < 2; j++) {
                unsigned base = insert1(t + j*NT, h12);
                float2 A0 = cur[base],        A1 = cur[base ^ m12];
                float2 P1 = pcur[base ^ p1m], P2 = pcur[base ^ p2m];
                float w1, w2, w1b, w2b;
                if (blk == 1) { w1 = -s1; w2 = -s2; w1b = w1; w2b = w2; }
                else {
                    unsigned k12  = base | (rank << 11);
                    unsigned k12b = k12 ^ m12;
                    w1  = par(k12  & X1) ? -s1 : s1;
                    w2  = par(k12  & X2) ? -s2 : s2;
                    w1b = par(k12b & X1) ? -s1 : s1;
                    w2b = par(k12b & X2) ? -s2 : s2;
                }
                {
                    float w1p = f1 ? -w1 : w1;
                    float T4 = -(w2 * w1p);
                    float k1 = c2 * w1, k2 = c1 * w2;
                    float2 r;
                    r.x = cc*A0.x - k1*P1.y - k2*P2.y + T4*A1.x;
                    r.y = cc*A0.y + k1*P1.x + k2*P2.x + T4*A1.y;
                    nxt[base] = r;
                }
                {
                    float w1p = f1 ? -w1b : w1b;
                    float T4 = -(w2b * w1p);
                    float k1 = c2 * w1b, k2 = c1 * w2b;
                    float2 r;
                    r.x = cc*A1.x - k1*P2.y - k2*P1.y + T4*A0.x;
                    r.y = cc*A1.y + k1*P2.x + k2*P1.x + T4*A0.y;
                    nxt[base ^ m12] = r;
                }
            }
            { float2* s = cur; cur = nxt; nxt = s; }
            { float2* s = pcur; pcur = pnxt; pnxt = s; }
            __syncthreads();
        }

        // ---- bias + trainable rots locals q0..q10 (q11 deferred) ----
        stage1q(gT2[blk], PL, blk, cur, rank, t);
    }

    // ---- final deferred bias(blk2)@q11 cross + measurement (fused, no barrier) ----
    float acc[NQ];
#pragma unroll
    for (int i = 0; i < NQ; i++) acc[i] = 0.0f;
    {
        const unsigned ma = PL.m1[2][11];
        const float2* g = gT2[2][11];
        const float2 gd = rank ? g[3] : g[0];
        const float2 go = rank ? g[2] : g[1];
        const unsigned pm = ma & 0x7FFu;
        cl.sync();
#pragma unroll
        for (int j = 0; j < 4; j++) {
            unsigned l = t + j*NT;
            float2 pv = pcur[l ^ pm];
            float2 a = cur[l];
            float2 r;
            r.x = gd.x*a.x - gd.y*a.y + go.x*pv.x - go.y*pv.y;
            r.y = gd.x*a.y + gd.y*a.x + go.x*pv.y + go.y*pv.x;
            float pr = r.x*r.x + r.y*r.y;
#pragma unroll
            for (int i = 0; i < NQ; i++) {
                unsigned Rm = PL.RM[i];
                int sg = par(l & Rm & 0x7FFu) ^ (rank & (Rm >> 11));
                acc[i] += sg ? -pr : pr;
            }
        }
    }
#pragma unroll
    for (int off = 16; off > 0; off >>= 1)
#pragma unroll
        for (int i = 0; i < NQ; i++)
            acc[i] += __shfl_down_sync(0xffffffffu, acc[i], off);
    const int wid = t >> 5;
    if ((t & 31) == 0) {
#pragma unroll
        for (int i = 0; i < NQ; i++) red[wid][i] = acc[i];
    }
    __syncthreads();
    if (t < NQ) {
        float s = 0.0f;
#pragma unroll
        for (int w = 0; w < NT/32; w++) s += red[w][t];
        sums[t] = s;
    }
    __syncthreads();
    cl.sync();
    if (rank == 0 && t < NQ)
        out[b*NQ + t] = sums[t] + psums[t];
    cl.sync();
}

// ---- host: GF(2) algebra of the CNOT ring ----
static inline unsigned Gm(unsigned j) {
    unsigned r = (j ^ (j >> 1)) & 0xFFFu;
    r ^= (j >> 11) & 1u;
    return r;
}
static inline unsigned Fm(unsigned k) {
    unsigned p = k;
    p ^= p >> 1; p ^= p >> 2; p ^= p >> 4; p ^= p >> 8;
    p &= 0xFFFu;
    return (p & 0xFFEu) | ((p ^ (k >> 11)) & 1u);
}

extern "C" void kernel_launch(void* const* d_in, const int* in_sizes, int n_in,
                              void* d_out, int out_size) {
    const float* data   = (const float*)d_in[0];
    const float* es     = (const float*)d_in[1];
    const float* eb     = (const float*)d_in[2];
    const float* eta    = (const float*)d_in[3];
    const float* ew_zz  = (const float*)d_in[4];
    const float* ew_xx  = (const float*)d_in[5];
    const float* ew_yy  = (const float*)d_in[6];
    const float* nb_z   = (const float*)d_in[7];
    const float* nb_x   = (const float*)d_in[8];
    const float* nb_y   = (const float*)d_in[9];
    const float* rots   = (const float*)d_in[10];
    float* out = (float*)d_out;

    Plan PL;
    unsigned rows[4][12];
    for (int p = 0; p < 4; p++) {
        unsigned col[12];
        for (int j = 0; j < 12; j++) {
            unsigned v = 1u << j;
            for (int it = 0; it < p; it++) v = Fm(v);
            col[j] = v;
        }
        for (int q = 0; q < 12; q++) {
            unsigned r = 0;
            for (int j = 0; j < 12; j++) r |= ((col[j] >> q) & 1u) << j;
            rows[p][q] = r;
        }
    }
    for (int blk = 0; blk < 3; blk++) {
        for (int q = 0; q < 12; q++) {
            unsigned m = 1u << q;
            for (int it = 0; it < blk; it++) m = Gm(m);
            PL.m1[blk][q] = (unsigned short)m;
            PL.R1[blk][q] = (unsigned short)rows[blk][q];
        }
        for (int e = 0; e < 12; e++) {
            unsigned a  = (e < 11) ? (unsigned)(11 - e) : 11u;
            unsigned b2 = (e < 11) ? (unsigned)(10 - e) : 0u;
            unsigned M = (1u << a) | (1u << b2);
            unsigned m = M;
            for (int it = 0; it < blk; it++) m = Gm(m);
            PL.mE[blk][e] = (unsigned short)m;
            PL.XE[blk][e] = (unsigned short)(rows[blk][a] ^ rows[blk][b2]);
        }
    }
    for (int i = 0; i < 12; i++) PL.RM[i] = (unsigned short)rows[3][11 - i];

    int B = in_sizes[0] / NQ;   // 64
    qsim_kernel<<<B * 2, NT>>>(data, es, eb, eta, ew_zz, ew_xx, ew_yy,
                               nb_z, nb_x, nb_y, rots, PL, out);
}

// round 7
// speedup vs baseline: 2.9583x; 1.0904x over previous
#include <cuda_runtime.h>
#include <cooperative_groups.h>
namespace cg = cooperative_groups;

#define NQ    12
#define HDIM  2048
#define NT    512

// ================= compile-time GF(2) plan =================
__host__ __device__ constexpr unsigned Gm_c(unsigned j) {
    unsigned r = (j ^ (j >> 1)) & 0xFFFu;
    r ^= (j >> 11) & 1u;
    return r;
}
__host__ __device__ constexpr unsigned Fm_c(unsigned k) {
    unsigned p = k;
    p ^= p >> 1; p ^= p >> 2; p ^= p >> 4; p ^= p >> 8;
    p &= 0xFFFu;
    return (p & 0xFFEu) | ((p ^ (k >> 11)) & 1u);
}
__host__ __device__ constexpr unsigned GmPow(unsigned v, int n) {
    for (int i = 0; i < n; i++) v = Gm_c(v);
    return v;
}
__host__ __device__ constexpr unsigned FmPow(unsigned v, int n) {
    for (int i = 0; i < n; i++) v = Fm_c(v);
    return v;
}
__host__ __device__ constexpr unsigned rowOf(int pw, int q) {
    unsigned r = 0;
    for (int j = 0; j < 12; j++)
        r |= ((FmPow(1u << j, pw) >> q) & 1u) << j;
    return r;
}
__host__ __device__ constexpr unsigned m1c(int blk, int q) { return GmPow(1u << q, blk); }
__host__ __device__ constexpr unsigned R1c(int blk, int q) { return rowOf(blk, q); }
__host__ __device__ constexpr unsigned mEc(int blk, int e) {
    unsigned a = e < 11 ? 11 - e : 11;
    unsigned b = e < 11 ? 10 - e : 0;
    return GmPow((1u << a) | (1u << b), blk);
}
__host__ __device__ constexpr unsigned XEc(int blk, int e) {
    int a = e < 11 ? 11 - e : 11;
    int b = e < 11 ? 10 - e : 0;
    return rowOf(blk, a) ^ rowOf(blk, b);
}
__host__ __device__ constexpr unsigned RMc(int i) { return rowOf(3, 11 - i); }
__host__ __device__ constexpr int topbit(unsigned m) { int h = 0; while (m >>= 1) h++; return h; }
__host__ __device__ constexpr int imin(int a, int b) { return a < b ? a : b; }
__host__ __device__ constexpr int imax(int a, int b) { return a > b ? a : b; }
__host__ __device__ constexpr int parc(unsigned x) { int c = 0; while (x) { c ^= (int)(x & 1u); x >>= 1; } return c; }

// ================= device math helpers =================
struct CM { float2 m[4]; };

__device__ __forceinline__ float2 cxmul(float2 a, float2 b) {
    return make_float2(a.x*b.x - a.y*b.y, a.x*b.y + a.y*b.x);
}
__device__ __forceinline__ float2 cxadd(float2 a, float2 b) {
    return make_float2(a.x + b.x, a.y + b.y);
}
__device__ __forceinline__ CM mm(const CM& A, const CM& B) {
    CM C;
#pragma unroll
    for (int i = 0; i < 2; i++)
#pragma unroll
        for (int j = 0; j < 2; j++)
            C.m[i*2+j] = cxadd(cxmul(A.m[i*2+0], B.m[0*2+j]),
                               cxmul(A.m[i*2+1], B.m[1*2+j]));
    return C;
}
__device__ __forceinline__ CM RX(float t) {
    float s, c; sincosf(0.5f*t, &s, &c);
    CM M;
    M.m[0] = make_float2(c,0.f);  M.m[1] = make_float2(0.f,-s);
    M.m[2] = make_float2(0.f,-s); M.m[3] = make_float2(c,0.f);
    return M;
}
__device__ __forceinline__ CM RY(float t) {
    float s, c; sincosf(0.5f*t, &s, &c);
    CM M;
    M.m[0] = make_float2(c,0.f); M.m[1] = make_float2(-s,0.f);
    M.m[2] = make_float2(s,0.f); M.m[3] = make_float2(c,0.f);
    return M;
}
__device__ __forceinline__ CM RZ(float t) {
    float s, c; sincosf(0.5f*t, &s, &c);
    CM M;
    M.m[0] = make_float2(c,-s);    M.m[1] = make_float2(0.f,0.f);
    M.m[2] = make_float2(0.f,0.f); M.m[3] = make_float2(c,s);
    return M;
}
__device__ __forceinline__ void apply2(const float2 g[4], float2 &a0, float2 &a1) {
    float2 n0, n1;
    n0.x = g[0].x*a0.x - g[0].y*a0.y + g[1].x*a1.x - g[1].y*a1.y;
    n0.y = g[0].x*a0.y + g[0].y*a0.x + g[1].x*a1.y + g[1].y*a1.x;
    n1.x = g[2].x*a0.x - g[2].y*a0.y + g[3].x*a1.x - g[3].y*a1.y;
    n1.y = g[2].x*a0.y + g[2].y*a0.x + g[3].x*a1.y + g[3].y*a1.x;
    a0 = n0; a1 = n1;
}
__device__ __forceinline__ void applyMix(float c, float ss, float2 &a, float2 &b) {
    float2 na, nb;
    na.x = c*a.x - ss*b.y;  na.y = c*a.y + ss*b.x;
    nb.x = c*b.x - ss*a.y;  nb.y = c*b.y + ss*a.x;
    a = na; b = nb;
}
__device__ __forceinline__ unsigned insert1(unsigned i, int h) {
    return ((i >> h) << (h + 1)) | (i & ((1u << h) - 1u));
}
__device__ __forceinline__ unsigned insert2(unsigned i, int lo, int hi) {
    unsigned p = ((i >> lo) << (lo + 1)) | (i & ((1u << lo) - 1u));
    p = ((p >> hi) << (hi + 1)) | (p & ((1u << hi) - 1u));
    return p;
}
__device__ __forceinline__ int par(unsigned x) { return __popc(x) & 1; }
__device__ __forceinline__ void cfma(float2& acc, float2 a, float2 b) {
    acc.x += a.x*b.x - a.y*b.y;
    acc.y += a.x*b.y + a.y*b.x;
}

// ================= templated sweeps (all masks are literals) =================
template<int BLK, int Q>
__device__ __forceinline__ void shflGate(const float2 (*gt)[4], float2 (&V)[4],
                                         unsigned base, unsigned rank)
{
    constexpr unsigned mc = m1c(BLK, Q), R = R1c(BLK, Q);
    unsigned bit = (unsigned)par(base & (R & 0x7FFu));
    if constexpr ((R >> 11) != 0) bit ^= rank;
    const float2 gd = bit ? gt[Q][3] : gt[Q][0];
    const float2 go = bit ? gt[Q][2] : gt[Q][1];
#pragma unroll
    for (int r = 0; r < 4; r++) {
        float px = __shfl_xor_sync(0xffffffffu, V[r].x, mc);
        float py = __shfl_xor_sync(0xffffffffu, V[r].y, mc);
        float2 nv;
        nv.x = gd.x*V[r].x - gd.y*V[r].y + go.x*px - go.y*py;
        nv.y = gd.x*V[r].y + gd.y*V[r].x + go.x*py + go.y*px;
        V[r] = nv;
    }
}

template<int BLK>
__device__ __forceinline__ void sweepA1q(const float2 (*gt)[4], float2* amp,
                                         unsigned rank, unsigned t)
{
    constexpr unsigned mA = m1c(BLK, 9),  RA = R1c(BLK, 9);
    constexpr unsigned mB = m1c(BLK, 10), RB = R1c(BLK, 10);
    constexpr int lo = imin(topbit(mA), topbit(mB));
    constexpr int hi = imax(topbit(mA), topbit(mB));
    unsigned p = insert2(t, lo, hi);
    unsigned base = p;
    unsigned fA = (unsigned)par(p & (RA & 0x7FFu));
    if constexpr ((RA >> 11) != 0) fA ^= rank;
    if (fA) base ^= mA;
    unsigned fB = (unsigned)par(p & (RB & 0x7FFu));
    if constexpr ((RB >> 11) != 0) fB ^= rank;
    if (fB) base ^= mB;
    float2 V[4];
    V[0] = amp[base];      V[1] = amp[base ^ mA];
    V[2] = amp[base ^ mB]; V[3] = amp[base ^ mA ^ mB];
    {
        float2 gA[4], gB[4];
#pragma unroll
        for (int k = 0; k < 4; k++) { gA[k] = gt[9][k]; gB[k] = gt[10][k]; }
        apply2(gA, V[0], V[1]); apply2(gA, V[2], V[3]);
        apply2(gB, V[0], V[2]); apply2(gB, V[1], V[3]);
    }
    shflGate<BLK,0>(gt, V, base, rank);
    shflGate<BLK,1>(gt, V, base, rank);
    shflGate<BLK,2>(gt, V, base, rank);
    shflGate<BLK,3>(gt, V, base, rank);
    shflGate<BLK,4>(gt, V, base, rank);
    amp[base] = V[0];      amp[base ^ mA] = V[1];
    amp[base ^ mB] = V[2]; amp[base ^ mA ^ mB] = V[3];
    __syncthreads();
}

template<int BLK, int QA, int QB, bool SYNC>
__device__ __forceinline__ void quadSweep(const float2 (*gt)[4], float2* amp,
                                          unsigned rank, unsigned t)
{
    constexpr unsigned mA = m1c(BLK, QA), RA = R1c(BLK, QA);
    constexpr unsigned mB = m1c(BLK, QB), RB = R1c(BLK, QB);
    constexpr int lo = imin(topbit(mA), topbit(mB));
    constexpr int hi = imax(topbit(mA), topbit(mB));
    unsigned p = insert2(t, lo, hi);
    unsigned base = p;
    unsigned fA = (unsigned)par(p & (RA & 0x7FFu));
    if constexpr ((RA >> 11) != 0) fA ^= rank;
    if (fA) base ^= mA;
    unsigned fB = (unsigned)par(p & (RB & 0x7FFu));
    if constexpr ((RB >> 11) != 0) fB ^= rank;
    if (fB) base ^= mB;
    float2 gA[4], gB[4];
#pragma unroll
    for (int k = 0; k < 4; k++) { gA[k] = gt[QA][k]; gB[k] = gt[QB][k]; }
    const unsigned i10 = base ^ mA, i01 = base ^ mB, i11 = base ^ mA ^ mB;
    float2 a00 = amp[base], a10 = amp[i10], a01 = amp[i01], a11 = amp[i11];
    apply2(gA, a00, a10); apply2(gA, a01, a11);
    apply2(gB, a00, a01); apply2(gB, a10, a11);
    amp[base] = a00; amp[i10] = a10; amp[i01] = a01; amp[i11] = a11;
    if constexpr (SYNC) __syncthreads();
}

template<int BLK, int E>
__device__ __forceinline__ void shflEdge(const float* sCb, const float* sSb,
                                         float2 (&V)[4], unsigned p, unsigned rank)
{
    constexpr unsigned mc = mEc(BLK, E);
    const float cc = sCb[E], sv = sSb[E];
    float ss;
    if constexpr (BLK == 1) {
        ss = -sv;
    } else {
        constexpr unsigned X = XEc(2, E);
        constexpr int bt = topbit(mc);
        constexpr unsigned mcx = (unsigned)parc(mc & X & 0x7FFu);
        unsigned sg = (unsigned)par(p & (X & 0x7FFu));
        if constexpr ((X >> 11) != 0) sg ^= rank;
        sg ^= ((p >> bt) & 1u) & mcx;
        ss = sg ? -sv : sv;
    }
#pragma unroll
    for (int r = 0; r < 4; r++) {
        float px = __shfl_xor_sync(0xffffffffu, V[r].x, mc);
        float py = __shfl_xor_sync(0xffffffffu, V[r].y, mc);
        float2 nv;
        nv.x = cc*V[r].x - ss*py;
        nv.y = cc*V[r].y + ss*px;
        V[r] = nv;
    }
}

template<int BLK, int E1, int E2, bool DOSHFL, bool SYNC>
__device__ __forceinline__ void isingSweep(const float* sCb, const float* sSb,
                                           float2* amp, unsigned rank, unsigned t)
{
    constexpr unsigned m1m = mEc(BLK, E1), m2m = mEc(BLK, E2);
    const float c1 = sCb[E1], s1 = sSb[E1];
    const float c2 = sCb[E2], s2 = sSb[E2];
    constexpr int lo = imin(topbit(m1m), topbit(m2m));
    constexpr int hi = imax(topbit(m1m), topbit(m2m));
    unsigned p = insert2(t, lo, hi);
    const unsigned iA = p ^ m1m, iB = p ^ m2m, iC = p ^ m1m ^ m2m;
    float2 V[4];
    V[0] = amp[p]; V[1] = amp[iA]; V[2] = amp[iB]; V[3] = amp[iC];
    if constexpr (BLK == 1) {
        applyMix(c1, -s1, V[0], V[1]); applyMix(c1, -s1, V[2], V[3]);
        applyMix(c2, -s2, V[0], V[2]); applyMix(c2, -s2, V[1], V[3]);
    } else {
        constexpr unsigned X1 = XEc(2, E1), X2 = XEc(2, E2);
        constexpr unsigned adj1 = (unsigned)parc(m2m & X1 & 0x7FFu);
        constexpr unsigned adj2 = (unsigned)parc(m1m & X2 & 0x7FFu);
        unsigned t1 = (unsigned)par(p & (X1 & 0x7FFu));
        if constexpr ((X1 >> 11) != 0) t1 ^= rank;
        applyMix(c1, t1 ? -s1 : s1, V[0], V[1]);
        applyMix(c1, (t1 ^ adj1) ? -s1 : s1, V[2], V[3]);
        unsigned t2 = (unsigned)par(p & (X2 & 0x7FFu));
        if constexpr ((X2 >> 11) != 0) t2 ^= rank;
        applyMix(c2, t2 ? -s2 : s2, V[0], V[2]);
        applyMix(c2, (t2 ^ adj2) ? -s2 : s2, V[1], V[3]);
    }
    if constexpr (DOSHFL) {
        shflEdge<BLK,7>(sCb, sSb, V, p, rank);
        shflEdge<BLK,8>(sCb, sSb, V, p, rank);
        shflEdge<BLK,9>(sCb, sSb, V, p, rank);
        shflEdge<BLK,10>(sCb, sSb, V, p, rank);
    }
    amp[p] = V[0]; amp[iA] = V[1]; amp[iB] = V[2]; amp[iC] = V[3];
    if constexpr (SYNC) __syncthreads();
}

template<int BLK>
__device__ __forceinline__ void cross1q(const float2* ga, const float2* gb,
                                        float2*& cur, float2*& nxt,
                                        float2*& pcur, float2*& pnxt,
                                        cg::cluster_group& cl,
                                        unsigned rank, unsigned t)
{
    constexpr unsigned ma = m1c(BLK-1, 11), mb = m1c(BLK, 11);
    const float2 ga_d  = rank ? ga[3] : ga[0];
    const float2 ga_o  = rank ? ga[2] : ga[1];
    const float2 ga_d2 = rank ? ga[0] : ga[3];
    const float2 ga_o2 = rank ? ga[1] : ga[2];
    const float2 gb_d  = rank ? gb[3] : gb[0];
    const float2 gb_o  = rank ? gb[2] : gb[1];
    const float2 C1 = cxmul(gb_d, ga_d);
    const float2 C2 = cxmul(gb_d, ga_o);
    const float2 C3 = cxmul(gb_o, ga_d2);
    const float2 C4 = cxmul(gb_o, ga_o2);
    constexpr unsigned m12 = (ma ^ mb) & 0x7FFu;
    constexpr int h12 = topbit(m12);
    constexpr unsigned pa = ma & 0x7FFu, pb = mb & 0x7FFu;
    cl.sync();
#pragma unroll
    for (int j = 0; j < 2; j++) {
        unsigned base = insert1(t + j*NT, h12);
        float2 r0 = cur[base],       r1 = cur[base ^ m12];
        float2 q0 = pcur[base ^ pa], q1 = pcur[base ^ pb];
        float2 o0 = make_float2(0.f, 0.f), o1 = make_float2(0.f, 0.f);
        cfma(o0, C1, r0); cfma(o0, C2, q0); cfma(o0, C3, q1); cfma(o0, C4, r1);
        cfma(o1, C1, r1); cfma(o1, C2, q1); cfma(o1, C3, q0); cfma(o1, C4, r0);
        nxt[base] = o0; nxt[base ^ m12] = o1;
    }
    { float2* s = cur; cur = nxt; nxt = s; }
    { float2* s = pcur; pcur = pnxt; pnxt = s; }
    __syncthreads();
}

template<int BLK>
__device__ __forceinline__ void crossE(const float* sCb, const float* sSb,
                                       float2*& cur, float2*& nxt,
                                       float2*& pcur, float2*& pnxt,
                                       cg::cluster_group& cl,
                                       unsigned rank, unsigned t)
{
    constexpr unsigned m1e = mEc(BLK, 11), m2e = mEc(BLK, 0);
    const float c1 = sCb[11], s1 = sSb[11];
    const float c2 = sCb[0],  s2 = sSb[0];
    const float cc = c1 * c2;
    constexpr unsigned X1 = XEc(2, 11), X2 = XEc(2, 0);
    constexpr int f1 = (BLK == 2) ? parc(mEc(2, 0) & XEc(2, 11) & 0xFFFu) : 0;
    constexpr unsigned m12 = (m1e ^ m2e) & 0x7FFu;
    constexpr int h12 = topbit(m12);
    constexpr unsigned p1m = m1e & 0x7FFu, p2m = m2e & 0x7FFu;
    cl.sync();
#pragma unroll
    for (int j = 0; j < 2; j++) {
        unsigned base = insert1(t + j*NT, h12);
        float2 A0 = cur[base],        A1 = cur[base ^ m12];
        float2 P1 = pcur[base ^ p1m], P2 = pcur[base ^ p2m];
        float w1, w2, w1b, w2b;
        if constexpr (BLK == 1) {
            w1 = -s1; w2 = -s2; w1b = w1; w2b = w2;
        } else {
            unsigned k12  = base | (rank << 11);
            unsigned k12b = k12 ^ m12;
            w1  = par(k12  & X1) ? -s1 : s1;
            w2  = par(k12  & X2) ? -s2 : s2;
            w1b = par(k12b & X1) ? -s1 : s1;
            w2b = par(k12b & X2) ? -s2 : s2;
        }
        {
            float w1p = f1 ? -w1 : w1;
            float T4 = -(w2 * w1p);
            float k1 = c2 * w1, k2 = c1 * w2;
            float2 r;
            r.x = cc*A0.x - k1*P1.y - k2*P2.y + T4*A1.x;
            r.y = cc*A0.y + k1*P1.x + k2*P2.x + T4*A1.y;
            nxt[base] = r;
        }
        {
            float w1p = f1 ? -w1b : w1b;
            float T4 = -(w2b * w1p);
            float k1 = c2 * w1b, k2 = c1 * w2b;
            float2 r;
            r.x = cc*A1.x - k1*P2.y - k2*P1.y + T4*A0.x;
            r.y = cc*A1.y + k1*P2.x + k2*P1.x + T4*A0.y;
            nxt[base ^ m12] = r;
        }
    }
    { float2* s = cur; cur = nxt; nxt = s; }
    { float2* s = pcur; pcur = pnxt; pnxt = s; }
    __syncthreads();
}

// ================= kernel =================
__global__ void __launch_bounds__(NT, 1) __cluster_dims__(2, 1, 1)
qsim_kernel(const float* __restrict__ data,
            const float* __restrict__ es,
            const float* __restrict__ eb,
            const float* __restrict__ eta,
            const float* __restrict__ ew_zz,
            const float* __restrict__ ew_xx,
            const float* __restrict__ ew_yy,
            const float* __restrict__ nb_z,
            const float* __restrict__ nb_x,
            const float* __restrict__ nb_y,
            const float* __restrict__ rots,
            float* __restrict__ out)
{
    __shared__ float2 ampA[HDIM];
    __shared__ float2 ampB[HDIM];
    __shared__ float2 gT1[3][NQ][4];
    __shared__ float2 gT2[3][NQ][4];
    __shared__ float  sC[3][NQ], sS[3][NQ], sH0[NQ];
    __shared__ float  red[NT/32][NQ];
    __shared__ float  sums[NQ];

    cg::cluster_group cl = cg::this_cluster();
    const unsigned rank = blockIdx.x & 1u;
    const int b = blockIdx.x >> 1;
    const unsigned t = threadIdx.x;
    float2* peerA = cl.map_shared_rank(ampA, rank ^ 1u);
    float2* peerB = cl.map_shared_rank(ampB, rank ^ 1u);
    float*  psums = cl.map_shared_rank(sums, 1u);

    // ---- all gate tables upfront, 36 threads ----
    if (t < 36) {
        const int blk = t / 12, q = t % 12;
        float d  = data[b*NQ + q];
        float ax = es[q*3+0]*d + eb[q*3+0];
        float ay = es[q*3+1]*d + eb[q*3+1];
        float az = es[q*3+2]*d + eb[q*3+2];
        CM M;
        if (blk == 0)      M = mm(RZ(az), mm(RY(ay), RX(ax)));
        else if (blk == 1) M = mm(RY(ay), RX(ax));
        else               M = mm(RZ(az), RY(ay));
#pragma unroll
        for (int k = 0; k < 4; k++) gT1[blk][q][k] = M.m[k];

        float bias = (blk == 0) ? nb_z[q] : (blk == 1) ? nb_x[q] : nb_y[q];
        CM Mb = (blk == 0) ? RZ(bias) : (blk == 1) ? RX(bias) : RY(bias);
        const float* rr = rots + blk*(NQ*3) + q*3;
        CM M2 = mm(RZ(rr[2]), mm(RY(rr[1]), mm(RX(rr[0]), Mb)));
#pragma unroll
        for (int k = 0; k < 4; k++) gT2[blk][q][k] = M2.m[k];

        float ew = (blk == 0) ? ew_zz[q] : (blk == 1) ? ew_xx[q] : ew_yy[q];
        float h = 0.5f * eta[blk] * ew;
        float s, c; sincosf(h, &s, &c);
        sC[blk][q] = c; sS[blk][q] = s;
        if (blk == 0) sH0[q] = h;
    }
    __syncthreads();

    float2* cur  = ampA;
    float2* nxt  = ampB;
    float2* pcur = peerA;
    float2* pnxt = peerB;

    // ---- blk0: product-state init + fused ZZ phase ----
    {
        float2 prod = rank ? gT1[0][11][2] : gT1[0][11][0];
#pragma unroll
        for (int q = 0; q < 9; q++) {
            float2 f = ((t >> q) & 1) ? gT1[0][q][2] : gT1[0][q][0];
            prod = cxmul(prod, f);
        }
        constexpr unsigned XE0v[12] = {
            XEc(0,0), XEc(0,1), XEc(0,2),  XEc(0,3),
            XEc(0,4), XEc(0,5), XEc(0,6),  XEc(0,7),
            XEc(0,8), XEc(0,9), XEc(0,10), XEc(0,11)
        };
#pragma unroll
        for (int j = 0; j < 4; j++) {
            unsigned l = t + j*NT;
            float2 v = cxmul(prod, (j & 1) ? gT1[0][9][2]  : gT1[0][9][0]);
            v = cxmul(v,           (j & 2) ? gT1[0][10][2] : gT1[0][10][0]);
            unsigned k12 = l | (rank << 11);
            float phi = 0.0f;
#pragma unroll
            for (int e = 0; e < 12; e++)
                phi += par(k12 & XE0v[e]) ? sH0[e] : -sH0[e];
            float sp, cp; __sincosf(phi, &sp, &cp);
            cur[l] = make_float2(v.x*cp - v.y*sp, v.x*sp + v.y*cp);
        }
        __syncthreads();
    }
    // blk0 bias+rots locals (q11 deferred); last sweep's sync covered by cl.sync
    sweepA1q<0>(gT2[0], cur, rank, t);
    quadSweep<0,5,6,true >(gT2[0], cur, rank, t);
    quadSweep<0,7,8,false>(gT2[0], cur, rank, t);

    // ======== block 1 ========
    cross1q<1>(gT2[0][11], gT1[1][11], cur, nxt, pcur, pnxt, cl, rank, t);
    sweepA1q<1>(gT1[1], cur, rank, t);
    quadSweep<1,5,6,true>(gT1[1], cur, rank, t);
    quadSweep<1,7,8,true>(gT1[1], cur, rank, t);
    isingSweep<1,1,2,true ,true >(sC[1], sS[1], cur, rank, t);
    isingSweep<1,3,4,false,true >(sC[1], sS[1], cur, rank, t);
    isingSweep<1,5,6,false,false>(sC[1], sS[1], cur, rank, t);
    crossE<1>(sC[1], sS[1], cur, nxt, pcur, pnxt, cl, rank, t);
    sweepA1q<1>(gT2[1], cur, rank, t);
    quadSweep<1,5,6,true >(gT2[1], cur, rank, t);
    quadSweep<1,7,8,false>(gT2[1], cur, rank, t);

    // ======== block 2 ========
    cross1q<2>(gT2[1][11], gT1[2][11], cur, nxt, pcur, pnxt, cl, rank, t);
    sweepA1q<2>(gT1[2], cur, rank, t);
    quadSweep<2,5,6,true>(gT1[2], cur, rank, t);
    quadSweep<2,7,8,true>(gT1[2], cur, rank, t);
    isingSweep<2,1,2,true ,true >(sC[2], sS[2], cur, rank, t);
    isingSweep<2,3,4,false,true >(sC[2], sS[2], cur, rank, t);
    isingSweep<2,5,6,false,false>(sC[2], sS[2], cur, rank, t);
    crossE<2>(sC[2], sS[2], cur, nxt, pcur, pnxt, cl, rank, t);
    sweepA1q<2>(gT2[2], cur, rank, t);
    quadSweep<2,5,6,true >(gT2[2], cur, rank, t);
    quadSweep<2,7,8,false>(gT2[2], cur, rank, t);

    // ---- final deferred bias(blk2)@q11 cross + measurement (fused) ----
    float acc[NQ];
#pragma unroll
    for (int i = 0; i < NQ; i++) acc[i] = 0.0f;
    {
        constexpr unsigned ma = m1c(2, 11);
        constexpr unsigned pm = ma & 0x7FFu;
        const float2* g = gT2[2][11];
        const float2 gd = rank ? g[3] : g[0];
        const float2 go = rank ? g[2] : g[1];
        constexpr unsigned RMv[12] = {
            RMc(0), RMc(1), RMc(2),  RMc(3),
            RMc(4), RMc(5), RMc(6),  RMc(7),
            RMc(8), RMc(9), RMc(10), RMc(11)
        };
        cl.sync();
#pragma unroll
        for (int j = 0; j < 4; j++) {
            unsigned l = t + j*NT;
            float2 pv = pcur[l ^ pm];
            float2 a = cur[l];
            float2 r;
            r.x = gd.x*a.x - gd.y*a.y + go.x*pv.x - go.y*pv.y;
            r.y = gd.x*a.y + gd.y*a.x + go.x*pv.y + go.y*pv.x;
            float pr = r.x*r.x + r.y*r.y;
#pragma unroll
            for (int i = 0; i < NQ; i++) {
                unsigned Rm = RMv[i];
                unsigned sg = (unsigned)par(l & (Rm & 0x7FFu));
                if (Rm >> 11) sg ^= rank;
                acc[i] += sg ? -pr : pr;
            }
        }
    }
#pragma unroll
    for (int off = 16; off > 0; off >>= 1)
#pragma unroll
        for (int i = 0; i < NQ; i++)
            acc[i] += __shfl_down_sync(0xffffffffu, acc[i], off);
    const int wid = t >> 5;
    if ((t & 31) == 0) {
#pragma unroll
        for (int i = 0; i < NQ; i++) red[wid][i] = acc[i];
    }
    __syncthreads();
    if (t < NQ) {
        float s = 0.0f;
#pragma unroll
        for (int w = 0; w < NT/32; w++) s += red[w][t];
        sums[t] = s;
    }
    __syncthreads();
    cl.sync();
    if (rank == 0 && t < NQ)
        out[b*NQ + t] = sums[t] + psums[t];
    cl.sync();
}

extern "C" void kernel_launch(void* const* d_in, const int* in_sizes, int n_in,
                              void* d_out, int out_size) {
    const float* data   = (const float*)d_in[0];
    const float* es     = (const float*)d_in[1];
    const float* eb     = (const float*)d_in[2];
    const float* eta    = (const float*)d_in[3];
    const float* ew_zz  = (const float*)d_in[4];
    const float* ew_xx  = (const float*)d_in[5];
    const float* ew_yy  = (const float*)d_in[6];
    const float* nb_z   = (const float*)d_in[7];
    const float* nb_x   = (const float*)d_in[8];
    const float* nb_y   = (const float*)d_in[9];
    const float* rots   = (const float*)d_in[10];
    float* out = (float*)d_out;

    int B = in_sizes[0] / NQ;   // 64
    qsim_kernel<<<B * 2, NT>>>(data, es, eb, eta, ew_zz, ew_xx, ew_yy,
                               nb_z, nb_x, nb_y, rots, out);
}